// round 4
// baseline (speedup 1.0000x reference)
#include <cuda_runtime.h>
#include <math.h>

#define N_NODES 100000
#define E_EDGES 800000
#define G_GRAPHS 512
#define HID 32
#define D_CUT 5.0f
#define TAB 8192

// ---------------- scratch (static, no allocation) ----------------
__device__ __align__(16) float g_ss[G_GRAPHS * 64];   // time MLP output per graph
__device__ __align__(16) float g_xm[N_NODES * 32];    // modulated x
__device__ __align__(16) float g_a[N_NODES * 32];     // x @ msg_w1[:32] + msg_b1
__device__ __align__(16) float g_b[N_NODES * 32];     // x @ msg_w1[32:]
__device__ __align__(16) float g_gate[N_NODES * 32];  // sigmoid(x @ gate_w + gate_b)
__device__ __align__(16) float g_macc[N_NODES * 32];  // segment_sum(m_ij) by j
__device__ __align__(16) float g_pacc[N_NODES * 4];   // pos sums (3) + count (1)
__device__ __align__(16) float4 g_pos4[N_NODES];      // padded positions
__device__ __align__(16) float g_tab[TAB * 32];       // dist_emb lookup table

__device__ __forceinline__ float siluf(float v) { return v / (1.0f + __expf(-v)); }
__device__ __forceinline__ float sigmf(float v) { return 1.0f / (1.0f + __expf(-v)); }

__device__ __forceinline__ void red_v4(float* p, float a, float b, float c, float d) {
    asm volatile("red.global.add.v4.f32 [%0], {%1,%2,%3,%4};"
                 :: "l"(p), "f"(a), "f"(b), "f"(c), "f"(d) : "memory");
}

// ---------------- K0: fused table build + time MLP ----------------
// blocks [0, TAB/8): dist_emb table rows; blocks [TAB/8, +G/4): time MLP.
__global__ void __launch_bounds__(256) k_prep(
        const float* __restrict__ means, const float* __restrict__ betas,
        const float* __restrict__ w_dist,
        const float* __restrict__ time,
        const float* __restrict__ w1, const float* __restrict__ b1,
        const float* __restrict__ w2, const float* __restrict__ b2) {
    int tid = threadIdx.x;
    if (blockIdx.x < TAB / 8) {
        __shared__ float sW[1024];
        __shared__ float sMu[32], sBeta[32];
        for (int k = tid; k < 1024; k += 256) sW[k] = w_dist[k];
        if (tid < 32) { sMu[tid] = means[tid]; sBeta[tid] = betas[tid]; }
        __syncthreads();

        int r = blockIdx.x * 8 + (tid >> 5);
        int c = tid & 31;
        float d = (float)r * (D_CUT / (float)(TAB - 1));
        float cutoff = 0.5f * (__cosf(d * (3.14159265358979f / D_CUT)) + 1.0f);
        float ed = __expf(-d);
        float acc = 0.0f;
        #pragma unroll 8
        for (int k = 0; k < 32; k++) {
            float t = ed - sMu[k];
            acc += __expf(-sBeta[k] * t * t) * sW[k * 32 + c];
        }
        g_tab[r * 32 + c] = cutoff * acc;
    } else {
        // time MLP: 4 graphs per block, 64 threads each
        __shared__ float trow[4][128];
        __shared__ float hid[4][64];
        int gsub = tid >> 6;
        int t = tid & 63;
        int g = (blockIdx.x - TAB / 8) * 4 + gsub;
        trow[gsub][t]      = time[g * 128 + t];
        trow[gsub][t + 64] = time[g * 128 + 64 + t];
        __syncthreads();
        float acc = b1[t];
        #pragma unroll 8
        for (int k = 0; k < 128; k++) acc += trow[gsub][k] * w1[k * 64 + t];
        hid[gsub][t] = siluf(acc);
        __syncthreads();
        float acc2 = b2[t];
        #pragma unroll 8
        for (int k = 0; k < 64; k++) acc2 += hid[gsub][k] * w2[k * 64 + t];
        g_ss[g * 64 + t] = acc2;
    }
}

// ---------------- K2: per-node precompute + accumulator zeroing ----------------
__global__ void __launch_bounds__(256) k_node(
        const float* __restrict__ x, const int* __restrict__ batch,
        const float* __restrict__ pos,
        const float* __restrict__ msg_w1, const float* __restrict__ msg_b1,
        const float* __restrict__ gate_w, const float* __restrict__ gate_b) {
    __shared__ __align__(16) float sW1[64 * 32];
    __shared__ __align__(16) float sWg[32 * 32];
    int tid = threadIdx.x;
    for (int k = tid; k < 2048; k += 256) sW1[k] = msg_w1[k];
    for (int k = tid; k < 1024; k += 256) sWg[k] = gate_w[k];
    __syncthreads();

    int sub = tid & 3;
    int c0 = sub * 8;
    int n = blockIdx.x * 64 + (tid >> 2);
    if (n >= N_NODES) return;   // warp-uniform (boundary at warp multiple)

    int bn = batch[n];
    const float4* scp = (const float4*)&g_ss[bn * 64 + c0];
    const float4* shp = (const float4*)&g_ss[bn * 64 + 32 + c0];
    const float4* xp  = (const float4*)&x[n * 32 + c0];
    float4 sc0 = scp[0], sc1 = scp[1];
    float4 sh0 = shp[0], sh1 = shp[1];
    float4 x0 = xp[0], x1 = xp[1];

    float xm[8];
    xm[0] = siluf(x0.x * (1.0f + sc0.x) + sh0.x);
    xm[1] = siluf(x0.y * (1.0f + sc0.y) + sh0.y);
    xm[2] = siluf(x0.z * (1.0f + sc0.z) + sh0.z);
    xm[3] = siluf(x0.w * (1.0f + sc0.w) + sh0.w);
    xm[4] = siluf(x1.x * (1.0f + sc1.x) + sh1.x);
    xm[5] = siluf(x1.y * (1.0f + sc1.y) + sh1.y);
    xm[6] = siluf(x1.z * (1.0f + sc1.z) + sh1.z);
    xm[7] = siluf(x1.w * (1.0f + sc1.w) + sh1.w);

    float a[8], b[8], ga[8];
    #pragma unroll
    for (int u = 0; u < 8; u++) {
        a[u] = msg_b1[c0 + u];
        b[u] = 0.0f;
        ga[u] = gate_b[c0 + u];
    }
    #pragma unroll
    for (int kk = 0; kk < 32; kk++) {
        float v = __shfl_sync(0xffffffffu, xm[kk & 7], kk >> 3, 4);
        const float4* wa = (const float4*)&sW1[kk * 32 + c0];
        const float4* wb = (const float4*)&sW1[(32 + kk) * 32 + c0];
        const float4* wg = (const float4*)&sWg[kk * 32 + c0];
        float4 a0 = wa[0], a1 = wa[1];
        float4 b0 = wb[0], b1v = wb[1];
        float4 g0 = wg[0], g1 = wg[1];
        a[0] += v * a0.x; a[1] += v * a0.y; a[2] += v * a0.z; a[3] += v * a0.w;
        a[4] += v * a1.x; a[5] += v * a1.y; a[6] += v * a1.z; a[7] += v * a1.w;
        b[0] += v * b0.x; b[1] += v * b0.y; b[2] += v * b0.z; b[3] += v * b0.w;
        b[4] += v * b1v.x; b[5] += v * b1v.y; b[6] += v * b1v.z; b[7] += v * b1v.w;
        ga[0] += v * g0.x; ga[1] += v * g0.y; ga[2] += v * g0.z; ga[3] += v * g0.w;
        ga[4] += v * g1.x; ga[5] += v * g1.y; ga[6] += v * g1.z; ga[7] += v * g1.w;
    }

    float4* outxm = (float4*)&g_xm[n * 32 + c0];
    outxm[0] = make_float4(xm[0], xm[1], xm[2], xm[3]);
    outxm[1] = make_float4(xm[4], xm[5], xm[6], xm[7]);
    float4* outa = (float4*)&g_a[n * 32 + c0];
    outa[0] = make_float4(a[0], a[1], a[2], a[3]);
    outa[1] = make_float4(a[4], a[5], a[6], a[7]);
    float4* outb = (float4*)&g_b[n * 32 + c0];
    outb[0] = make_float4(b[0], b[1], b[2], b[3]);
    outb[1] = make_float4(b[4], b[5], b[6], b[7]);
    float4* outg = (float4*)&g_gate[n * 32 + c0];
    outg[0] = make_float4(sigmf(ga[0]), sigmf(ga[1]), sigmf(ga[2]), sigmf(ga[3]));
    outg[1] = make_float4(sigmf(ga[4]), sigmf(ga[5]), sigmf(ga[6]), sigmf(ga[7]));

    float4 z = make_float4(0.f, 0.f, 0.f, 0.f);
    float4* mz = (float4*)&g_macc[n * 32 + c0];
    mz[0] = z; mz[1] = z;
    if (sub == 0) {
        *(float4*)&g_pacc[n * 4] = z;
        g_pos4[n] = make_float4(pos[n * 3], pos[n * 3 + 1], pos[n * 3 + 2], 0.0f);
    }
}

// ---------------- K3: edge kernel (NE=2, 3 blocks/SM) ----------------
#define MV32X2(accA, accB, inA, inB, W, c0)                                      \
    do {                                                                         \
        _Pragma("unroll")                                                        \
        for (int kk = 0; kk < 32; kk++) {                                        \
            float vA = __shfl_sync(0xffffffffu, inA[kk & 7], kk >> 3, 4);        \
            float vB = __shfl_sync(0xffffffffu, inB[kk & 7], kk >> 3, 4);        \
            const float4* wp = (const float4*)&W[kk * 32 + c0];                  \
            float4 w0 = wp[0];                                                   \
            float4 w1 = wp[1];                                                   \
            accA[0] += vA * w0.x; accA[1] += vA * w0.y;                          \
            accA[2] += vA * w0.z; accA[3] += vA * w0.w;                          \
            accA[4] += vA * w1.x; accA[5] += vA * w1.y;                          \
            accA[6] += vA * w1.z; accA[7] += vA * w1.w;                          \
            accB[0] += vB * w0.x; accB[1] += vB * w0.y;                          \
            accB[2] += vB * w0.z; accB[3] += vB * w0.w;                          \
            accB[4] += vB * w1.x; accB[5] += vB * w1.y;                          \
            accB[6] += vB * w1.z; accB[7] += vB * w1.w;                          \
        }                                                                        \
    } while (0)

__global__ void __launch_bounds__(256, 3) k_edge(
        const int* __restrict__ ei,
        const float* __restrict__ msg_w2, const float* __restrict__ msg_b2,
        const float* __restrict__ coord_w1, const float* __restrict__ coord_b1,
        const float* __restrict__ coord_w2, const float* __restrict__ coord_b2) {
    __shared__ __align__(16) float sW2[1024];
    __shared__ __align__(16) float sC1[1024];
    __shared__ float sC2[32], sB2[32], sCB1[32];
    __shared__ float sCB2;

    int tid = threadIdx.x;
    for (int k = tid; k < 1024; k += 256) {
        sW2[k] = msg_w2[k];
        sC1[k] = coord_w1[k];
    }
    if (tid < 32) {
        sC2[tid]  = coord_w2[tid];
        sB2[tid]  = msg_b2[tid];
        sCB1[tid] = coord_b1[tid];
    }
    if (tid == 0) sCB2 = coord_b2[0];
    __syncthreads();

    int sub = tid & 3;
    int c0 = sub * 8;
    int e0 = blockIdx.x * 128 + (tid >> 2) * 2; // E = 800000 = 6250*128 exactly

    int2 ip = *(const int2*)&ei[e0];
    int2 jp = *(const int2*)&ei[E_EDGES + e0];
    int iA = ip.x, iB = ip.y;
    int jA = jp.x, jB = jp.y;

    // positions (padded float4, broadcast within group)
    float4 piA = g_pos4[iA], pjA = g_pos4[jA];
    float4 piB = g_pos4[iB], pjB = g_pos4[jB];
    float dxA = piA.x - pjA.x, dyA = piA.y - pjA.y, dzA = piA.z - pjA.z;
    float dxB = piB.x - pjB.x, dyB = piB.y - pjB.y, dzB = piB.z - pjB.z;
    float distA = sqrtf(dxA * dxA + dyA * dyA + dzA * dzA);
    float distB = sqrtf(dxB * dxB + dyB * dyB + dzB * dzB);

    float uA = fminf(distA, D_CUT) * ((float)(TAB - 1) / D_CUT);
    float uB = fminf(distB, D_CUT) * ((float)(TAB - 1) / D_CUT);
    int i0A = min((int)uA, TAB - 2);
    int i0B = min((int)uB, TAB - 2);
    float frA = uA - (float)i0A;
    float frB = uB - (float)i0B;

    // h = silu(a_i + b_j)
    float hA[8], hB[8];
    {
        const float4* ap = (const float4*)&g_a[iA * 32 + c0];
        const float4* bp = (const float4*)&g_b[jA * 32 + c0];
        float4 a0 = ap[0], a1 = ap[1], b0 = bp[0], b1 = bp[1];
        hA[0] = siluf(a0.x + b0.x); hA[1] = siluf(a0.y + b0.y);
        hA[2] = siluf(a0.z + b0.z); hA[3] = siluf(a0.w + b0.w);
        hA[4] = siluf(a1.x + b1.x); hA[5] = siluf(a1.y + b1.y);
        hA[6] = siluf(a1.z + b1.z); hA[7] = siluf(a1.w + b1.w);
    }
    {
        const float4* ap = (const float4*)&g_a[iB * 32 + c0];
        const float4* bp = (const float4*)&g_b[jB * 32 + c0];
        float4 a0 = ap[0], a1 = ap[1], b0 = bp[0], b1 = bp[1];
        hB[0] = siluf(a0.x + b0.x); hB[1] = siluf(a0.y + b0.y);
        hB[2] = siluf(a0.z + b0.z); hB[3] = siluf(a0.w + b0.w);
        hB[4] = siluf(a1.x + b1.x); hB[5] = siluf(a1.y + b1.y);
        hB[6] = siluf(a1.z + b1.z); hB[7] = siluf(a1.w + b1.w);
    }

    float mmA[8], mmB[8];
    #pragma unroll
    for (int u = 0; u < 8; u++) { mmA[u] = sB2[c0 + u]; mmB[u] = sB2[c0 + u]; }
    MV32X2(mmA, mmB, hA, hB, sW2, c0);

    // tab+gate loads AFTER MV1 (keeps eg out of MV1's live range)
    float mA[8], mB[8];
    {
        const float4* t0 = (const float4*)&g_tab[i0A * 32 + c0];
        const float4* t1 = (const float4*)&g_tab[(i0A + 1) * 32 + c0];
        const float4* gp = (const float4*)&g_gate[jA * 32 + c0];
        float4 a0 = t0[0], a1 = t0[1], b0 = t1[0], b1 = t1[1];
        float4 g0 = gp[0], g1 = gp[1];
        mA[0] = siluf(mmA[0]) * (a0.x + frA * (b0.x - a0.x)) * g0.x;
        mA[1] = siluf(mmA[1]) * (a0.y + frA * (b0.y - a0.y)) * g0.y;
        mA[2] = siluf(mmA[2]) * (a0.z + frA * (b0.z - a0.z)) * g0.z;
        mA[3] = siluf(mmA[3]) * (a0.w + frA * (b0.w - a0.w)) * g0.w;
        mA[4] = siluf(mmA[4]) * (a1.x + frA * (b1.x - a1.x)) * g1.x;
        mA[5] = siluf(mmA[5]) * (a1.y + frA * (b1.y - a1.y)) * g1.y;
        mA[6] = siluf(mmA[6]) * (a1.z + frA * (b1.z - a1.z)) * g1.z;
        mA[7] = siluf(mmA[7]) * (a1.w + frA * (b1.w - a1.w)) * g1.w;
    }
    {
        const float4* t0 = (const float4*)&g_tab[i0B * 32 + c0];
        const float4* t1 = (const float4*)&g_tab[(i0B + 1) * 32 + c0];
        const float4* gp = (const float4*)&g_gate[jB * 32 + c0];
        float4 a0 = t0[0], a1 = t0[1], b0 = t1[0], b1 = t1[1];
        float4 g0 = gp[0], g1 = gp[1];
        mB[0] = siluf(mmB[0]) * (a0.x + frB * (b0.x - a0.x)) * g0.x;
        mB[1] = siluf(mmB[1]) * (a0.y + frB * (b0.y - a0.y)) * g0.y;
        mB[2] = siluf(mmB[2]) * (a0.z + frB * (b0.z - a0.z)) * g0.z;
        mB[3] = siluf(mmB[3]) * (a0.w + frB * (b0.w - a0.w)) * g0.w;
        mB[4] = siluf(mmB[4]) * (a1.x + frB * (b1.x - a1.x)) * g1.x;
        mB[5] = siluf(mmB[5]) * (a1.y + frB * (b1.y - a1.y)) * g1.y;
        mB[6] = siluf(mmB[6]) * (a1.z + frB * (b1.z - a1.z)) * g1.z;
        mB[7] = siluf(mmB[7]) * (a1.w + frB * (b1.w - a1.w)) * g1.w;
    }

    // scatter m_ij early (retire atomics while MV2 runs)
    float* maccA = &g_macc[jA * 32 + c0];
    red_v4(maccA,     mA[0], mA[1], mA[2], mA[3]);
    red_v4(maccA + 4, mA[4], mA[5], mA[6], mA[7]);
    float* maccB = &g_macc[jB * 32 + c0];
    red_v4(maccB,     mB[0], mB[1], mB[2], mB[3]);
    red_v4(maccB + 4, mB[4], mB[5], mB[6], mB[7]);

    float stA[8], stB[8];
    #pragma unroll
    for (int u = 0; u < 8; u++) { stA[u] = sCB1[c0 + u]; stB[u] = sCB1[c0 + u]; }
    MV32X2(stA, stB, mA, mB, sC1, c0);

    float spA = 0.0f, spB = 0.0f;
    #pragma unroll
    for (int u = 0; u < 8; u++) {
        float w = sC2[c0 + u];
        spA += siluf(stA[u]) * w;
        spB += siluf(stB[u]) * w;
    }
    spA += __shfl_xor_sync(0xffffffffu, spA, 1);
    spA += __shfl_xor_sync(0xffffffffu, spA, 2);
    spB += __shfl_xor_sync(0xffffffffu, spB, 1);
    spB += __shfl_xor_sync(0xffffffffu, spB, 2);
    float sA = spA + sCB2;
    float sB = spB + sCB2;

    if (sub == 0) {
        red_v4(&g_pacc[jA * 4], dxA * sA, dyA * sA, dzA * sA, 1.0f);
        red_v4(&g_pacc[jB * 4], dxB * sB, dyB * sB, dzB * sB, 1.0f);
    }
}

// ---------------- K4: combine + outputs ----------------
#define MV32(accv, inv, W, c0)                                                   \
    do {                                                                         \
        _Pragma("unroll")                                                        \
        for (int kk = 0; kk < 32; kk++) {                                        \
            float v = __shfl_sync(0xffffffffu, inv[kk & 7], kk >> 3, 4);         \
            const float4* wp = (const float4*)&W[kk * 32 + c0];                  \
            float4 w0 = wp[0];                                                   \
            float4 w1 = wp[1];                                                   \
            accv[0] += v * w0.x; accv[1] += v * w0.y;                            \
            accv[2] += v * w0.z; accv[3] += v * w0.w;                            \
            accv[4] += v * w1.x; accv[5] += v * w1.y;                            \
            accv[6] += v * w1.z; accv[7] += v * w1.w;                            \
        }                                                                        \
    } while (0)

__global__ void __launch_bounds__(256) k_final(
        const float* __restrict__ pos,
        const float* __restrict__ comb_w1, const float* __restrict__ cb1,
        const float* __restrict__ comb_w2, const float* __restrict__ cb2,
        float* __restrict__ outx, float* __restrict__ outp) {
    __shared__ __align__(16) float sW1[64 * 32];
    __shared__ __align__(16) float sW2[32 * 32];
    int tid = threadIdx.x;
    for (int k = tid; k < 2048; k += 256) sW1[k] = comb_w1[k];
    for (int k = tid; k < 1024; k += 256) sW2[k] = comb_w2[k];
    __syncthreads();

    int sub = tid & 3;
    int c0 = sub * 8;
    int n = blockIdx.x * 64 + (tid >> 2);
    if (n >= N_NODES) return;   // warp-uniform

    const float* src = (sub < 2) ? &g_xm[n * 32] : &g_macc[n * 32];
    const float4* ip = (const float4*)&src[(sub & 1) * 16];
    float4 i0 = ip[0], i1 = ip[1], i2 = ip[2], i3 = ip[3];
    float inv[16] = {i0.x, i0.y, i0.z, i0.w, i1.x, i1.y, i1.z, i1.w,
                     i2.x, i2.y, i2.z, i2.w, i3.x, i3.y, i3.z, i3.w};

    float acc[8];
    #pragma unroll
    for (int w = 0; w < 8; w++) acc[w] = cb1[c0 + w];
    #pragma unroll
    for (int kk = 0; kk < 64; kk++) {
        float v = __shfl_sync(0xffffffffu, inv[kk & 15], kk >> 4, 4);
        const float4* wp = (const float4*)&sW1[kk * 32 + c0];
        float4 w0 = wp[0], w1 = wp[1];
        acc[0] += v * w0.x; acc[1] += v * w0.y; acc[2] += v * w0.z; acc[3] += v * w0.w;
        acc[4] += v * w1.x; acc[5] += v * w1.y; acc[6] += v * w1.z; acc[7] += v * w1.w;
    }
    float hh[8];
    #pragma unroll
    for (int w = 0; w < 8; w++) hh[w] = siluf(acc[w]);

    float acc2[8];
    #pragma unroll
    for (int w = 0; w < 8; w++) acc2[w] = cb2[c0 + w];
    MV32(acc2, hh, sW2, c0);

    const float4* xmp = (const float4*)&g_xm[n * 32 + c0];
    float4 xm0 = xmp[0], xm1 = xmp[1];
    float4 o0, o1;
    o0.x = siluf(xm0.x + acc2[0]); o0.y = siluf(xm0.y + acc2[1]);
    o0.z = siluf(xm0.z + acc2[2]); o0.w = siluf(xm0.w + acc2[3]);
    o1.x = siluf(xm1.x + acc2[4]); o1.y = siluf(xm1.y + acc2[5]);
    o1.z = siluf(xm1.z + acc2[6]); o1.w = siluf(xm1.w + acc2[7]);
    float4* op = (float4*)&outx[n * 32 + c0];
    op[0] = o0; op[1] = o1;

    if (sub == 0) {
        float4 pa = *(const float4*)&g_pacc[n * 4];
        float inv_c = 1.0f / fmaxf(pa.w, 1.0f);
        outp[n * 3 + 0] = pos[n * 3 + 0] + pa.x * inv_c;
        outp[n * 3 + 1] = pos[n * 3 + 1] + pa.y * inv_c;
        outp[n * 3 + 2] = pos[n * 3 + 2] + pa.z * inv_c;
    }
}

// ---------------- launch ----------------
extern "C" void kernel_launch(void* const* d_in, const int* in_sizes, int n_in,
                              void* d_out, int out_size) {
    const float* x        = (const float*)d_in[0];
    const int*   ei       = (const int*)d_in[1];
    const float* pos      = (const float*)d_in[2];
    const float* time     = (const float*)d_in[3];
    const int*   batch    = (const int*)d_in[4];
    const float* means    = (const float*)d_in[5];
    const float* betas    = (const float*)d_in[6];
    const float* w_dist   = (const float*)d_in[7];
    const float* msg_w1   = (const float*)d_in[8];
    const float* msg_b1   = (const float*)d_in[9];
    const float* msg_w2   = (const float*)d_in[10];
    const float* msg_b2   = (const float*)d_in[11];
    const float* gate_w   = (const float*)d_in[12];
    const float* gate_b   = (const float*)d_in[13];
    const float* time_w1  = (const float*)d_in[14];
    const float* time_b1  = (const float*)d_in[15];
    const float* time_w2  = (const float*)d_in[16];
    const float* time_b2  = (const float*)d_in[17];
    const float* comb_w1  = (const float*)d_in[18];
    const float* comb_b1  = (const float*)d_in[19];
    const float* comb_w2  = (const float*)d_in[20];
    const float* comb_b2  = (const float*)d_in[21];
    const float* coord_w1 = (const float*)d_in[22];
    const float* coord_b1 = (const float*)d_in[23];
    const float* coord_w2 = (const float*)d_in[24];
    const float* coord_b2 = (const float*)d_in[25];

    float* outx = (float*)d_out;
    float* outp = (float*)d_out + N_NODES * 32;

    k_prep<<<TAB / 8 + G_GRAPHS / 4, 256>>>(means, betas, w_dist,
                                            time, time_w1, time_b1, time_w2, time_b2);
    k_node<<<(N_NODES + 63) / 64, 256>>>(x, batch, pos, msg_w1, msg_b1, gate_w, gate_b);
    k_edge<<<E_EDGES / 128, 256>>>(ei, msg_w2, msg_b2,
                                   coord_w1, coord_b1, coord_w2, coord_b2);
    k_final<<<(N_NODES + 63) / 64, 256>>>(pos, comb_w1, comb_b1, comb_w2, comb_b2,
                                          outx, outp);
}

// round 5
// speedup vs baseline: 1.4800x; 1.4800x over previous
#include <cuda_runtime.h>
#include <math.h>

#define N_NODES 100000
#define E_EDGES 800000
#define G_GRAPHS 512
#define HID 32
#define D_CUT 5.0f
#define TAB 8192

// ---------------- scratch (static, no allocation) ----------------
__device__ __align__(16) float g_ss[G_GRAPHS * 64];   // time MLP output per graph
__device__ __align__(16) float g_xm[N_NODES * 32];    // modulated x
__device__ __align__(16) float g_a[N_NODES * 32];     // x @ msg_w1[:32] + msg_b1
__device__ __align__(16) float g_b[N_NODES * 32];     // x @ msg_w1[32:]
__device__ __align__(16) float g_gate[N_NODES * 32];  // sigmoid(x @ gate_w + gate_b)
__device__ __align__(16) float g_macc[N_NODES * 32];  // segment_sum(m_ij) by j
__device__ __align__(16) float g_pacc[N_NODES * 4];   // pos sums (3) + count (1)
__device__ __align__(16) float4 g_pos4[N_NODES];      // padded positions
__device__ __align__(16) float g_tab[TAB * 32];       // dist_emb lookup table

__device__ __forceinline__ float siluf(float v) { return v / (1.0f + __expf(-v)); }
__device__ __forceinline__ float sigmf(float v) { return 1.0f / (1.0f + __expf(-v)); }

__device__ __forceinline__ void red_v4(float* p, float a, float b, float c, float d) {
    asm volatile("red.global.add.v4.f32 [%0], {%1,%2,%3,%4};"
                 :: "l"(p), "f"(a), "f"(b), "f"(c), "f"(d) : "memory");
}

// ---------------- K0: fused table build + time MLP ----------------
__global__ void __launch_bounds__(256) k_prep(
        const float* __restrict__ means, const float* __restrict__ betas,
        const float* __restrict__ w_dist,
        const float* __restrict__ time,
        const float* __restrict__ w1, const float* __restrict__ b1,
        const float* __restrict__ w2, const float* __restrict__ b2) {
    int tid = threadIdx.x;
    if (blockIdx.x < TAB / 8) {
        __shared__ float sW[1024];
        __shared__ float sMu[32], sBeta[32];
        for (int k = tid; k < 1024; k += 256) sW[k] = w_dist[k];
        if (tid < 32) { sMu[tid] = means[tid]; sBeta[tid] = betas[tid]; }
        __syncthreads();

        int r = blockIdx.x * 8 + (tid >> 5);
        int c = tid & 31;
        float d = (float)r * (D_CUT / (float)(TAB - 1));
        float cutoff = 0.5f * (__cosf(d * (3.14159265358979f / D_CUT)) + 1.0f);
        float ed = __expf(-d);
        float acc = 0.0f;
        #pragma unroll 8
        for (int k = 0; k < 32; k++) {
            float t = ed - sMu[k];
            acc += __expf(-sBeta[k] * t * t) * sW[k * 32 + c];
        }
        g_tab[r * 32 + c] = cutoff * acc;
    } else {
        __shared__ float trow[4][128];
        __shared__ float hid[4][64];
        int gsub = tid >> 6;
        int t = tid & 63;
        int g = (blockIdx.x - TAB / 8) * 4 + gsub;
        trow[gsub][t]      = time[g * 128 + t];
        trow[gsub][t + 64] = time[g * 128 + 64 + t];
        __syncthreads();
        float acc = b1[t];
        #pragma unroll 8
        for (int k = 0; k < 128; k++) acc += trow[gsub][k] * w1[k * 64 + t];
        hid[gsub][t] = siluf(acc);
        __syncthreads();
        float acc2 = b2[t];
        #pragma unroll 8
        for (int k = 0; k < 64; k++) acc2 += hid[gsub][k] * w2[k * 64 + t];
        g_ss[g * 64 + t] = acc2;
    }
}

// ---------------- K2: per-node precompute + accumulator zeroing ----------------
__global__ void __launch_bounds__(256) k_node(
        const float* __restrict__ x, const int* __restrict__ batch,
        const float* __restrict__ pos,
        const float* __restrict__ msg_w1, const float* __restrict__ msg_b1,
        const float* __restrict__ gate_w, const float* __restrict__ gate_b) {
    __shared__ __align__(16) float sW1[64 * 32];
    __shared__ __align__(16) float sWg[32 * 32];
    int tid = threadIdx.x;
    for (int k = tid; k < 2048; k += 256) sW1[k] = msg_w1[k];
    for (int k = tid; k < 1024; k += 256) sWg[k] = gate_w[k];
    __syncthreads();

    int sub = tid & 3;
    int c0 = sub * 8;
    int n = blockIdx.x * 64 + (tid >> 2);
    if (n >= N_NODES) return;   // warp-uniform (boundary at warp multiple)

    int bn = batch[n];
    const float4* scp = (const float4*)&g_ss[bn * 64 + c0];
    const float4* shp = (const float4*)&g_ss[bn * 64 + 32 + c0];
    const float4* xp  = (const float4*)&x[n * 32 + c0];
    float4 sc0 = scp[0], sc1 = scp[1];
    float4 sh0 = shp[0], sh1 = shp[1];
    float4 x0 = xp[0], x1 = xp[1];

    float xm[8];
    xm[0] = siluf(x0.x * (1.0f + sc0.x) + sh0.x);
    xm[1] = siluf(x0.y * (1.0f + sc0.y) + sh0.y);
    xm[2] = siluf(x0.z * (1.0f + sc0.z) + sh0.z);
    xm[3] = siluf(x0.w * (1.0f + sc0.w) + sh0.w);
    xm[4] = siluf(x1.x * (1.0f + sc1.x) + sh1.x);
    xm[5] = siluf(x1.y * (1.0f + sc1.y) + sh1.y);
    xm[6] = siluf(x1.z * (1.0f + sc1.z) + sh1.z);
    xm[7] = siluf(x1.w * (1.0f + sc1.w) + sh1.w);

    float a[8], b[8], ga[8];
    #pragma unroll
    for (int u = 0; u < 8; u++) {
        a[u] = msg_b1[c0 + u];
        b[u] = 0.0f;
        ga[u] = gate_b[c0 + u];
    }
    #pragma unroll
    for (int kk = 0; kk < 32; kk++) {
        float v = __shfl_sync(0xffffffffu, xm[kk & 7], kk >> 3, 4);
        const float4* wa = (const float4*)&sW1[kk * 32 + c0];
        const float4* wb = (const float4*)&sW1[(32 + kk) * 32 + c0];
        const float4* wg = (const float4*)&sWg[kk * 32 + c0];
        float4 a0 = wa[0], a1 = wa[1];
        float4 b0 = wb[0], b1v = wb[1];
        float4 g0 = wg[0], g1 = wg[1];
        a[0] += v * a0.x; a[1] += v * a0.y; a[2] += v * a0.z; a[3] += v * a0.w;
        a[4] += v * a1.x; a[5] += v * a1.y; a[6] += v * a1.z; a[7] += v * a1.w;
        b[0] += v * b0.x; b[1] += v * b0.y; b[2] += v * b0.z; b[3] += v * b0.w;
        b[4] += v * b1v.x; b[5] += v * b1v.y; b[6] += v * b1v.z; b[7] += v * b1v.w;
        ga[0] += v * g0.x; ga[1] += v * g0.y; ga[2] += v * g0.z; ga[3] += v * g0.w;
        ga[4] += v * g1.x; ga[5] += v * g1.y; ga[6] += v * g1.z; ga[7] += v * g1.w;
    }

    float4* outxm = (float4*)&g_xm[n * 32 + c0];
    outxm[0] = make_float4(xm[0], xm[1], xm[2], xm[3]);
    outxm[1] = make_float4(xm[4], xm[5], xm[6], xm[7]);
    float4* outa = (float4*)&g_a[n * 32 + c0];
    outa[0] = make_float4(a[0], a[1], a[2], a[3]);
    outa[1] = make_float4(a[4], a[5], a[6], a[7]);
    float4* outb = (float4*)&g_b[n * 32 + c0];
    outb[0] = make_float4(b[0], b[1], b[2], b[3]);
    outb[1] = make_float4(b[4], b[5], b[6], b[7]);
    float4* outg = (float4*)&g_gate[n * 32 + c0];
    outg[0] = make_float4(sigmf(ga[0]), sigmf(ga[1]), sigmf(ga[2]), sigmf(ga[3]));
    outg[1] = make_float4(sigmf(ga[4]), sigmf(ga[5]), sigmf(ga[6]), sigmf(ga[7]));

    float4 z = make_float4(0.f, 0.f, 0.f, 0.f);
    float4* mz = (float4*)&g_macc[n * 32 + c0];
    mz[0] = z; mz[1] = z;
    if (sub == 0) {
        *(float4*)&g_pacc[n * 4] = z;
        g_pos4[n] = make_float4(pos[n * 3], pos[n * 3 + 1], pos[n * 3 + 2], 0.0f);
    }
}

// ---------------- K3: edge kernel (NE=2, 128-thread blocks) ----------------
// 128 threads = 32 groups x 4 lanes; each group handles 2 adjacent edges.
// Natural register allocation (~86) -> 5 blocks/SM = 20 warps (vs 16 at 256thr).
#define MV32X2(accA, accB, inA, inB, W, c0)                                      \
    do {                                                                         \
        _Pragma("unroll")                                                        \
        for (int kk = 0; kk < 32; kk++) {                                        \
            float vA = __shfl_sync(0xffffffffu, inA[kk & 7], kk >> 3, 4);        \
            float vB = __shfl_sync(0xffffffffu, inB[kk & 7], kk >> 3, 4);        \
            const float4* wp = (const float4*)&W[kk * 32 + c0];                  \
            float4 w0 = wp[0];                                                   \
            float4 w1 = wp[1];                                                   \
            accA[0] += vA * w0.x; accA[1] += vA * w0.y;                          \
            accA[2] += vA * w0.z; accA[3] += vA * w0.w;                          \
            accA[4] += vA * w1.x; accA[5] += vA * w1.y;                          \
            accA[6] += vA * w1.z; accA[7] += vA * w1.w;                          \
            accB[0] += vB * w0.x; accB[1] += vB * w0.y;                          \
            accB[2] += vB * w0.z; accB[3] += vB * w0.w;                          \
            accB[4] += vB * w1.x; accB[5] += vB * w1.y;                          \
            accB[6] += vB * w1.z; accB[7] += vB * w1.w;                          \
        }                                                                        \
    } while (0)

__global__ void __launch_bounds__(128) k_edge(
        const int* __restrict__ ei,
        const float* __restrict__ msg_w2, const float* __restrict__ msg_b2,
        const float* __restrict__ coord_w1, const float* __restrict__ coord_b1,
        const float* __restrict__ coord_w2, const float* __restrict__ coord_b2) {
    __shared__ __align__(16) float sW2[1024];
    __shared__ __align__(16) float sC1[1024];
    __shared__ float sC2[32], sB2[32], sCB1[32];
    __shared__ float sCB2;

    int tid = threadIdx.x;
    for (int k = tid; k < 1024; k += 128) {
        sW2[k] = msg_w2[k];
        sC1[k] = coord_w1[k];
    }
    if (tid < 32) {
        sC2[tid]  = coord_w2[tid];
        sB2[tid]  = msg_b2[tid];
        sCB1[tid] = coord_b1[tid];
    }
    if (tid == 0) sCB2 = coord_b2[0];
    __syncthreads();

    int sub = tid & 3;
    int c0 = sub * 8;
    int e0 = blockIdx.x * 64 + (tid >> 2) * 2; // E = 800000 = 12500*64 exactly

    int2 ip = *(const int2*)&ei[e0];
    int2 jp = *(const int2*)&ei[E_EDGES + e0];
    int iA = ip.x, iB = ip.y;
    int jA = jp.x, jB = jp.y;

    // positions (padded float4, broadcast within group)
    float4 piA = g_pos4[iA], pjA = g_pos4[jA];
    float4 piB = g_pos4[iB], pjB = g_pos4[jB];
    float dxA = piA.x - pjA.x, dyA = piA.y - pjA.y, dzA = piA.z - pjA.z;
    float dxB = piB.x - pjB.x, dyB = piB.y - pjB.y, dzB = piB.z - pjB.z;
    float distA = sqrtf(dxA * dxA + dyA * dyA + dzA * dzA);
    float distB = sqrtf(dxB * dxB + dyB * dyB + dzB * dzB);

    // dist_emb via table lookup + lerp, fused with gate -> eg = emb * gate
    float uA = fminf(distA, D_CUT) * ((float)(TAB - 1) / D_CUT);
    float uB = fminf(distB, D_CUT) * ((float)(TAB - 1) / D_CUT);
    int i0A = min((int)uA, TAB - 2);
    int i0B = min((int)uB, TAB - 2);
    float frA = uA - (float)i0A;
    float frB = uB - (float)i0B;

    const float4* tA0 = (const float4*)&g_tab[i0A * 32 + c0];
    const float4* tA1 = (const float4*)&g_tab[(i0A + 1) * 32 + c0];
    const float4* tB0 = (const float4*)&g_tab[i0B * 32 + c0];
    const float4* tB1 = (const float4*)&g_tab[(i0B + 1) * 32 + c0];
    const float4* gAp = (const float4*)&g_gate[jA * 32 + c0];
    const float4* gBp = (const float4*)&g_gate[jB * 32 + c0];

    float egA[8], egB[8];
    {
        float4 a0 = tA0[0], a1 = tA0[1], b0 = tA1[0], b1 = tA1[1];
        float4 g0 = gAp[0], g1 = gAp[1];
        egA[0] = (a0.x + frA * (b0.x - a0.x)) * g0.x;
        egA[1] = (a0.y + frA * (b0.y - a0.y)) * g0.y;
        egA[2] = (a0.z + frA * (b0.z - a0.z)) * g0.z;
        egA[3] = (a0.w + frA * (b0.w - a0.w)) * g0.w;
        egA[4] = (a1.x + frA * (b1.x - a1.x)) * g1.x;
        egA[5] = (a1.y + frA * (b1.y - a1.y)) * g1.y;
        egA[6] = (a1.z + frA * (b1.z - a1.z)) * g1.z;
        egA[7] = (a1.w + frA * (b1.w - a1.w)) * g1.w;
    }
    {
        float4 a0 = tB0[0], a1 = tB0[1], b0 = tB1[0], b1 = tB1[1];
        float4 g0 = gBp[0], g1 = gBp[1];
        egB[0] = (a0.x + frB * (b0.x - a0.x)) * g0.x;
        egB[1] = (a0.y + frB * (b0.y - a0.y)) * g0.y;
        egB[2] = (a0.z + frB * (b0.z - a0.z)) * g0.z;
        egB[3] = (a0.w + frB * (b0.w - a0.w)) * g0.w;
        egB[4] = (a1.x + frB * (b1.x - a1.x)) * g1.x;
        egB[5] = (a1.y + frB * (b1.y - a1.y)) * g1.y;
        egB[6] = (a1.z + frB * (b1.z - a1.z)) * g1.z;
        egB[7] = (a1.w + frB * (b1.w - a1.w)) * g1.w;
    }

    // h = silu(a_i + b_j)
    float hA[8], hB[8];
    {
        const float4* ap = (const float4*)&g_a[iA * 32 + c0];
        const float4* bp = (const float4*)&g_b[jA * 32 + c0];
        float4 a0 = ap[0], a1 = ap[1], b0 = bp[0], b1 = bp[1];
        hA[0] = siluf(a0.x + b0.x); hA[1] = siluf(a0.y + b0.y);
        hA[2] = siluf(a0.z + b0.z); hA[3] = siluf(a0.w + b0.w);
        hA[4] = siluf(a1.x + b1.x); hA[5] = siluf(a1.y + b1.y);
        hA[6] = siluf(a1.z + b1.z); hA[7] = siluf(a1.w + b1.w);
    }
    {
        const float4* ap = (const float4*)&g_a[iB * 32 + c0];
        const float4* bp = (const float4*)&g_b[jB * 32 + c0];
        float4 a0 = ap[0], a1 = ap[1], b0 = bp[0], b1 = bp[1];
        hB[0] = siluf(a0.x + b0.x); hB[1] = siluf(a0.y + b0.y);
        hB[2] = siluf(a0.z + b0.z); hB[3] = siluf(a0.w + b0.w);
        hB[4] = siluf(a1.x + b1.x); hB[5] = siluf(a1.y + b1.y);
        hB[6] = siluf(a1.z + b1.z); hB[7] = siluf(a1.w + b1.w);
    }

    float mmA[8], mmB[8];
    #pragma unroll
    for (int u = 0; u < 8; u++) { mmA[u] = sB2[c0 + u]; mmB[u] = sB2[c0 + u]; }
    MV32X2(mmA, mmB, hA, hB, sW2, c0);

    float mA[8], mB[8];
    #pragma unroll
    for (int u = 0; u < 8; u++) {
        mA[u] = siluf(mmA[u]) * egA[u];
        mB[u] = siluf(mmB[u]) * egB[u];
    }

    // scatter m_ij early (retire atomics while MV2 runs)
    float* maccA = &g_macc[jA * 32 + c0];
    red_v4(maccA,     mA[0], mA[1], mA[2], mA[3]);
    red_v4(maccA + 4, mA[4], mA[5], mA[6], mA[7]);
    float* maccB = &g_macc[jB * 32 + c0];
    red_v4(maccB,     mB[0], mB[1], mB[2], mB[3]);
    red_v4(maccB + 4, mB[4], mB[5], mB[6], mB[7]);

    float stA[8], stB[8];
    #pragma unroll
    for (int u = 0; u < 8; u++) { stA[u] = sCB1[c0 + u]; stB[u] = sCB1[c0 + u]; }
    MV32X2(stA, stB, mA, mB, sC1, c0);

    float spA = 0.0f, spB = 0.0f;
    #pragma unroll
    for (int u = 0; u < 8; u++) {
        float w = sC2[c0 + u];
        spA += siluf(stA[u]) * w;
        spB += siluf(stB[u]) * w;
    }
    spA += __shfl_xor_sync(0xffffffffu, spA, 1);
    spA += __shfl_xor_sync(0xffffffffu, spA, 2);
    spB += __shfl_xor_sync(0xffffffffu, spB, 1);
    spB += __shfl_xor_sync(0xffffffffu, spB, 2);
    float sA = spA + sCB2;
    float sB = spB + sCB2;

    if (sub == 0) {
        red_v4(&g_pacc[jA * 4], dxA * sA, dyA * sA, dzA * sA, 1.0f);
        red_v4(&g_pacc[jB * 4], dxB * sB, dyB * sB, dzB * sB, 1.0f);
    }
}

// ---------------- K4: combine + outputs ----------------
#define MV32(accv, inv, W, c0)                                                   \
    do {                                                                         \
        _Pragma("unroll")                                                        \
        for (int kk = 0; kk < 32; kk++) {                                        \
            float v = __shfl_sync(0xffffffffu, inv[kk & 7], kk >> 3, 4);         \
            const float4* wp = (const float4*)&W[kk * 32 + c0];                  \
            float4 w0 = wp[0];                                                   \
            float4 w1 = wp[1];                                                   \
            accv[0] += v * w0.x; accv[1] += v * w0.y;                            \
            accv[2] += v * w0.z; accv[3] += v * w0.w;                            \
            accv[4] += v * w1.x; accv[5] += v * w1.y;                            \
            accv[6] += v * w1.z; accv[7] += v * w1.w;                            \
        }                                                                        \
    } while (0)

__global__ void __launch_bounds__(256) k_final(
        const float* __restrict__ pos,
        const float* __restrict__ comb_w1, const float* __restrict__ cb1,
        const float* __restrict__ comb_w2, const float* __restrict__ cb2,
        float* __restrict__ outx, float* __restrict__ outp) {
    __shared__ __align__(16) float sW1[64 * 32];
    __shared__ __align__(16) float sW2[32 * 32];
    int tid = threadIdx.x;
    for (int k = tid; k < 2048; k += 256) sW1[k] = comb_w1[k];
    for (int k = tid; k < 1024; k += 256) sW2[k] = comb_w2[k];
    __syncthreads();

    int sub = tid & 3;
    int c0 = sub * 8;
    int n = blockIdx.x * 64 + (tid >> 2);
    if (n >= N_NODES) return;   // warp-uniform

    const float* src = (sub < 2) ? &g_xm[n * 32] : &g_macc[n * 32];
    const float4* ip = (const float4*)&src[(sub & 1) * 16];
    float4 i0 = ip[0], i1 = ip[1], i2 = ip[2], i3 = ip[3];
    float inv[16] = {i0.x, i0.y, i0.z, i0.w, i1.x, i1.y, i1.z, i1.w,
                     i2.x, i2.y, i2.z, i2.w, i3.x, i3.y, i3.z, i3.w};

    float acc[8];
    #pragma unroll
    for (int w = 0; w < 8; w++) acc[w] = cb1[c0 + w];
    #pragma unroll
    for (int kk = 0; kk < 64; kk++) {
        float v = __shfl_sync(0xffffffffu, inv[kk & 15], kk >> 4, 4);
        const float4* wp = (const float4*)&sW1[kk * 32 + c0];
        float4 w0 = wp[0], w1 = wp[1];
        acc[0] += v * w0.x; acc[1] += v * w0.y; acc[2] += v * w0.z; acc[3] += v * w0.w;
        acc[4] += v * w1.x; acc[5] += v * w1.y; acc[6] += v * w1.z; acc[7] += v * w1.w;
    }
    float hh[8];
    #pragma unroll
    for (int w = 0; w < 8; w++) hh[w] = siluf(acc[w]);

    float acc2[8];
    #pragma unroll
    for (int w = 0; w < 8; w++) acc2[w] = cb2[c0 + w];
    MV32(acc2, hh, sW2, c0);

    const float4* xmp = (const float4*)&g_xm[n * 32 + c0];
    float4 xm0 = xmp[0], xm1 = xmp[1];
    float4 o0, o1;
    o0.x = siluf(xm0.x + acc2[0]); o0.y = siluf(xm0.y + acc2[1]);
    o0.z = siluf(xm0.z + acc2[2]); o0.w = siluf(xm0.w + acc2[3]);
    o1.x = siluf(xm1.x + acc2[4]); o1.y = siluf(xm1.y + acc2[5]);
    o1.z = siluf(xm1.z + acc2[6]); o1.w = siluf(xm1.w + acc2[7]);
    float4* op = (float4*)&outx[n * 32 + c0];
    op[0] = o0; op[1] = o1;

    if (sub == 0) {
        float4 pa = *(const float4*)&g_pacc[n * 4];
        float inv_c = 1.0f / fmaxf(pa.w, 1.0f);
        outp[n * 3 + 0] = pos[n * 3 + 0] + pa.x * inv_c;
        outp[n * 3 + 1] = pos[n * 3 + 1] + pa.y * inv_c;
        outp[n * 3 + 2] = pos[n * 3 + 2] + pa.z * inv_c;
    }
}

// ---------------- launch ----------------
extern "C" void kernel_launch(void* const* d_in, const int* in_sizes, int n_in,
                              void* d_out, int out_size) {
    const float* x        = (const float*)d_in[0];
    const int*   ei       = (const int*)d_in[1];
    const float* pos      = (const float*)d_in[2];
    const float* time     = (const float*)d_in[3];
    const int*   batch    = (const int*)d_in[4];
    const float* means    = (const float*)d_in[5];
    const float* betas    = (const float*)d_in[6];
    const float* w_dist   = (const float*)d_in[7];
    const float* msg_w1   = (const float*)d_in[8];
    const float* msg_b1   = (const float*)d_in[9];
    const float* msg_w2   = (const float*)d_in[10];
    const float* msg_b2   = (const float*)d_in[11];
    const float* gate_w   = (const float*)d_in[12];
    const float* gate_b   = (const float*)d_in[13];
    const float* time_w1  = (const float*)d_in[14];
    const float* time_b1  = (const float*)d_in[15];
    const float* time_w2  = (const float*)d_in[16];
    const float* time_b2  = (const float*)d_in[17];
    const float* comb_w1  = (const float*)d_in[18];
    const float* comb_b1  = (const float*)d_in[19];
    const float* comb_w2  = (const float*)d_in[20];
    const float* comb_b2  = (const float*)d_in[21];
    const float* coord_w1 = (const float*)d_in[22];
    const float* coord_b1 = (const float*)d_in[23];
    const float* coord_w2 = (const float*)d_in[24];
    const float* coord_b2 = (const float*)d_in[25];

    float* outx = (float*)d_out;
    float* outp = (float*)d_out + N_NODES * 32;

    k_prep<<<TAB / 8 + G_GRAPHS / 4, 256>>>(means, betas, w_dist,
                                            time, time_w1, time_b1, time_w2, time_b2);
    k_node<<<(N_NODES + 63) / 64, 256>>>(x, batch, pos, msg_w1, msg_b1, gate_w, gate_b);
    k_edge<<<E_EDGES / 64, 128>>>(ei, msg_w2, msg_b2,
                                  coord_w1, coord_b1, coord_w2, coord_b2);
    k_final<<<(N_NODES + 63) / 64, 256>>>(pos, comb_w1, comb_b1, comb_w2, comb_b2,
                                          outx, outp);
}

// round 6
// speedup vs baseline: 1.5509x; 1.0479x over previous
#include <cuda_runtime.h>
#include <math.h>

#define N_NODES 100000
#define E_EDGES 800000
#define G_GRAPHS 512
#define HID 32
#define D_CUT 5.0f
#define TAB 8192
#define NODE_BLOCKS 1563   // ceil(100000/64)

typedef unsigned long long u64;

// ---------------- scratch (static, no allocation) ----------------
__device__ __align__(16) float g_ss[G_GRAPHS * 64];
__device__ __align__(16) float g_xm[N_NODES * 32];
__device__ __align__(16) float g_a[N_NODES * 32];
__device__ __align__(16) float g_b[N_NODES * 32];
__device__ __align__(16) float g_gate[N_NODES * 32];
__device__ __align__(16) float g_macc[N_NODES * 32];
__device__ __align__(16) float g_pacc[N_NODES * 4];
__device__ __align__(16) float4 g_pos4[N_NODES];
__device__ __align__(16) float g_tab[TAB * 32];

__device__ __forceinline__ float siluf(float v) { return v / (1.0f + __expf(-v)); }
__device__ __forceinline__ float sigmf(float v) { return 1.0f / (1.0f + __expf(-v)); }

__device__ __forceinline__ void red_v4(float* p, float a, float b, float c, float d) {
    asm volatile("red.global.add.v4.f32 [%0], {%1,%2,%3,%4};"
                 :: "l"(p), "f"(a), "f"(b), "f"(c), "f"(d) : "memory");
}

// packed f32x2 helpers (sm_103a native; .rn rounding identical to scalar FFMA)
__device__ __forceinline__ u64 pack2(float lo, float hi) {
    u64 r; asm("mov.b64 %0, {%1, %2};" : "=l"(r) : "f"(lo), "f"(hi)); return r;
}
__device__ __forceinline__ void unpack2(u64 v, float& lo, float& hi) {
    asm("mov.b64 {%0, %1}, %2;" : "=f"(lo), "=f"(hi) : "l"(v));
}
__device__ __forceinline__ void ffma2(u64& d, u64 a, u64 b) {
    asm("fma.rn.f32x2 %0, %1, %2, %0;" : "+l"(d) : "l"(a), "l"(b));
}

// ---------------- K1: time MLP (G x 128 -> G x 64) ----------------
__global__ void __launch_bounds__(256) k_time(
        const float* __restrict__ time,
        const float* __restrict__ w1, const float* __restrict__ b1,
        const float* __restrict__ w2, const float* __restrict__ b2) {
    __shared__ float trow[4][128];
    __shared__ float hid[4][64];
    int tid = threadIdx.x;
    int gsub = tid >> 6;
    int t = tid & 63;
    int g = blockIdx.x * 4 + gsub;
    trow[gsub][t]      = time[g * 128 + t];
    trow[gsub][t + 64] = time[g * 128 + 64 + t];
    __syncthreads();
    float acc = b1[t];
    #pragma unroll 8
    for (int k = 0; k < 128; k++) acc += trow[gsub][k] * w1[k * 64 + t];
    hid[gsub][t] = siluf(acc);
    __syncthreads();
    float acc2 = b2[t];
    #pragma unroll 8
    for (int k = 0; k < 64; k++) acc2 += hid[gsub][k] * w2[k * 64 + t];
    g_ss[g * 64 + t] = acc2;
}

// ---------------- K2: per-node precompute (+ fused dist_emb table build) ----
__global__ void __launch_bounds__(256) k_node(
        const float* __restrict__ x, const int* __restrict__ batch,
        const float* __restrict__ pos,
        const float* __restrict__ msg_w1, const float* __restrict__ msg_b1,
        const float* __restrict__ gate_w, const float* __restrict__ gate_b,
        const float* __restrict__ means, const float* __restrict__ betas,
        const float* __restrict__ w_dist) {
    __shared__ __align__(16) float sW1[64 * 32];
    __shared__ __align__(16) float sWg[32 * 32];
    __shared__ float sMu[32], sBeta[32];
    int tid = threadIdx.x;

    if (blockIdx.x >= NODE_BLOCKS) {
        // ---- dist_emb table branch ----
        for (int k = tid; k < 1024; k += 256) sW1[k] = w_dist[k];
        if (tid < 32) { sMu[tid] = means[tid]; sBeta[tid] = betas[tid]; }
        __syncthreads();
        int r = (blockIdx.x - NODE_BLOCKS) * 8 + (tid >> 5);
        int c = tid & 31;
        float d = (float)r * (D_CUT / (float)(TAB - 1));
        float cutoff = 0.5f * (__cosf(d * (3.14159265358979f / D_CUT)) + 1.0f);
        float ed = __expf(-d);
        float acc = 0.0f;
        #pragma unroll 8
        for (int k = 0; k < 32; k++) {
            float t = ed - sMu[k];
            acc += __expf(-sBeta[k] * t * t) * sW1[k * 32 + c];
        }
        g_tab[r * 32 + c] = cutoff * acc;
        return;
    }

    for (int k = tid; k < 2048; k += 256) sW1[k] = msg_w1[k];
    for (int k = tid; k < 1024; k += 256) sWg[k] = gate_w[k];
    __syncthreads();

    int sub = tid & 3;
    int c0 = sub * 8;
    int n = blockIdx.x * 64 + (tid >> 2);
    if (n >= N_NODES) return;   // warp-uniform

    int bn = batch[n];
    const float4* scp = (const float4*)&g_ss[bn * 64 + c0];
    const float4* shp = (const float4*)&g_ss[bn * 64 + 32 + c0];
    const float4* xp  = (const float4*)&x[n * 32 + c0];
    float4 sc0 = scp[0], sc1 = scp[1];
    float4 sh0 = shp[0], sh1 = shp[1];
    float4 x0 = xp[0], x1 = xp[1];

    float xm[8];
    xm[0] = siluf(x0.x * (1.0f + sc0.x) + sh0.x);
    xm[1] = siluf(x0.y * (1.0f + sc0.y) + sh0.y);
    xm[2] = siluf(x0.z * (1.0f + sc0.z) + sh0.z);
    xm[3] = siluf(x0.w * (1.0f + sc0.w) + sh0.w);
    xm[4] = siluf(x1.x * (1.0f + sc1.x) + sh1.x);
    xm[5] = siluf(x1.y * (1.0f + sc1.y) + sh1.y);
    xm[6] = siluf(x1.z * (1.0f + sc1.z) + sh1.z);
    xm[7] = siluf(x1.w * (1.0f + sc1.w) + sh1.w);

    u64 a2[4], b2[4], ga2[4];
    #pragma unroll
    for (int p = 0; p < 4; p++) {
        a2[p]  = pack2(msg_b1[c0 + 2 * p], msg_b1[c0 + 2 * p + 1]);
        b2[p]  = 0ULL;
        ga2[p] = pack2(gate_b[c0 + 2 * p], gate_b[c0 + 2 * p + 1]);
    }
    #pragma unroll
    for (int kk = 0; kk < 32; kk++) {
        float v = __shfl_sync(0xffffffffu, xm[kk & 7], kk >> 3, 4);
        u64 vv = pack2(v, v);
        const ulonglong2* wa = (const ulonglong2*)&sW1[kk * 32 + c0];
        const ulonglong2* wb = (const ulonglong2*)&sW1[(32 + kk) * 32 + c0];
        const ulonglong2* wg = (const ulonglong2*)&sWg[kk * 32 + c0];
        ulonglong2 wa0 = wa[0], wa1 = wa[1];
        ulonglong2 wb0 = wb[0], wb1 = wb[1];
        ulonglong2 wg0 = wg[0], wg1 = wg[1];
        ffma2(a2[0], wa0.x, vv); ffma2(a2[1], wa0.y, vv);
        ffma2(a2[2], wa1.x, vv); ffma2(a2[3], wa1.y, vv);
        ffma2(b2[0], wb0.x, vv); ffma2(b2[1], wb0.y, vv);
        ffma2(b2[2], wb1.x, vv); ffma2(b2[3], wb1.y, vv);
        ffma2(ga2[0], wg0.x, vv); ffma2(ga2[1], wg0.y, vv);
        ffma2(ga2[2], wg1.x, vv); ffma2(ga2[3], wg1.y, vv);
    }

    float4* outxm = (float4*)&g_xm[n * 32 + c0];
    outxm[0] = make_float4(xm[0], xm[1], xm[2], xm[3]);
    outxm[1] = make_float4(xm[4], xm[5], xm[6], xm[7]);

    ulonglong2* outa = (ulonglong2*)&g_a[n * 32 + c0];
    outa[0] = make_ulonglong2(a2[0], a2[1]);
    outa[1] = make_ulonglong2(a2[2], a2[3]);
    ulonglong2* outb = (ulonglong2*)&g_b[n * 32 + c0];
    outb[0] = make_ulonglong2(b2[0], b2[1]);
    outb[1] = make_ulonglong2(b2[2], b2[3]);

    float g[8];
    unpack2(ga2[0], g[0], g[1]); unpack2(ga2[1], g[2], g[3]);
    unpack2(ga2[2], g[4], g[5]); unpack2(ga2[3], g[6], g[7]);
    float4* outg = (float4*)&g_gate[n * 32 + c0];
    outg[0] = make_float4(sigmf(g[0]), sigmf(g[1]), sigmf(g[2]), sigmf(g[3]));
    outg[1] = make_float4(sigmf(g[4]), sigmf(g[5]), sigmf(g[6]), sigmf(g[7]));

    float4 z = make_float4(0.f, 0.f, 0.f, 0.f);
    float4* mz = (float4*)&g_macc[n * 32 + c0];
    mz[0] = z; mz[1] = z;
    if (sub == 0) {
        *(float4*)&g_pacc[n * 4] = z;
        g_pos4[n] = make_float4(pos[n * 3], pos[n * 3 + 1], pos[n * 3 + 2], 0.0f);
    }
}

// ---------------- K3: edge kernel (NE=2, 128 threads, FFMA2 matvecs) --------
#define MV32X2(accA, accB, inA, inB, W, c0)                                      \
    do {                                                                         \
        _Pragma("unroll")                                                        \
        for (int kk = 0; kk < 32; kk++) {                                        \
            float vA = __shfl_sync(0xffffffffu, inA[kk & 7], kk >> 3, 4);        \
            float vB = __shfl_sync(0xffffffffu, inB[kk & 7], kk >> 3, 4);        \
            u64 vvA = pack2(vA, vA);                                             \
            u64 vvB = pack2(vB, vB);                                             \
            const ulonglong2* wp = (const ulonglong2*)&W[kk * 32 + c0];          \
            ulonglong2 w0 = wp[0], w1 = wp[1];                                   \
            ffma2(accA[0], w0.x, vvA); ffma2(accA[1], w0.y, vvA);                \
            ffma2(accA[2], w1.x, vvA); ffma2(accA[3], w1.y, vvA);                \
            ffma2(accB[0], w0.x, vvB); ffma2(accB[1], w0.y, vvB);                \
            ffma2(accB[2], w1.x, vvB); ffma2(accB[3], w1.y, vvB);                \
        }                                                                        \
    } while (0)

__global__ void __launch_bounds__(128) k_edge(
        const int* __restrict__ ei,
        const float* __restrict__ msg_w2, const float* __restrict__ msg_b2,
        const float* __restrict__ coord_w1, const float* __restrict__ coord_b1,
        const float* __restrict__ coord_w2, const float* __restrict__ coord_b2) {
    __shared__ __align__(16) float sW2[1024];
    __shared__ __align__(16) float sC1[1024];
    __shared__ float sC2[32], sB2[32], sCB1[32];
    __shared__ float sCB2;

    int tid = threadIdx.x;
    for (int k = tid; k < 1024; k += 128) {
        sW2[k] = msg_w2[k];
        sC1[k] = coord_w1[k];
    }
    if (tid < 32) {
        sC2[tid]  = coord_w2[tid];
        sB2[tid]  = msg_b2[tid];
        sCB1[tid] = coord_b1[tid];
    }
    if (tid == 0) sCB2 = coord_b2[0];
    __syncthreads();

    int sub = tid & 3;
    int c0 = sub * 8;
    int e0 = blockIdx.x * 64 + (tid >> 2) * 2; // E = 800000 = 12500*64 exactly

    int2 ip = *(const int2*)&ei[e0];
    int2 jp = *(const int2*)&ei[E_EDGES + e0];
    int iA = ip.x, iB = ip.y;
    int jA = jp.x, jB = jp.y;

    float4 piA = g_pos4[iA], pjA = g_pos4[jA];
    float4 piB = g_pos4[iB], pjB = g_pos4[jB];
    float dxA = piA.x - pjA.x, dyA = piA.y - pjA.y, dzA = piA.z - pjA.z;
    float dxB = piB.x - pjB.x, dyB = piB.y - pjB.y, dzB = piB.z - pjB.z;
    float distA = sqrtf(dxA * dxA + dyA * dyA + dzA * dzA);
    float distB = sqrtf(dxB * dxB + dyB * dyB + dzB * dzB);

    float uA = fminf(distA, D_CUT) * ((float)(TAB - 1) / D_CUT);
    float uB = fminf(distB, D_CUT) * ((float)(TAB - 1) / D_CUT);
    int i0A = min((int)uA, TAB - 2);
    int i0B = min((int)uB, TAB - 2);
    float frA = uA - (float)i0A;
    float frB = uB - (float)i0B;

    const float4* tA0 = (const float4*)&g_tab[i0A * 32 + c0];
    const float4* tA1 = (const float4*)&g_tab[(i0A + 1) * 32 + c0];
    const float4* tB0 = (const float4*)&g_tab[i0B * 32 + c0];
    const float4* tB1 = (const float4*)&g_tab[(i0B + 1) * 32 + c0];
    const float4* gAp = (const float4*)&g_gate[jA * 32 + c0];
    const float4* gBp = (const float4*)&g_gate[jB * 32 + c0];

    float egA[8], egB[8];
    {
        float4 a0 = tA0[0], a1 = tA0[1], b0 = tA1[0], b1 = tA1[1];
        float4 g0 = gAp[0], g1 = gAp[1];
        egA[0] = (a0.x + frA * (b0.x - a0.x)) * g0.x;
        egA[1] = (a0.y + frA * (b0.y - a0.y)) * g0.y;
        egA[2] = (a0.z + frA * (b0.z - a0.z)) * g0.z;
        egA[3] = (a0.w + frA * (b0.w - a0.w)) * g0.w;
        egA[4] = (a1.x + frA * (b1.x - a1.x)) * g1.x;
        egA[5] = (a1.y + frA * (b1.y - a1.y)) * g1.y;
        egA[6] = (a1.z + frA * (b1.z - a1.z)) * g1.z;
        egA[7] = (a1.w + frA * (b1.w - a1.w)) * g1.w;
    }
    {
        float4 a0 = tB0[0], a1 = tB0[1], b0 = tB1[0], b1 = tB1[1];
        float4 g0 = gBp[0], g1 = gBp[1];
        egB[0] = (a0.x + frB * (b0.x - a0.x)) * g0.x;
        egB[1] = (a0.y + frB * (b0.y - a0.y)) * g0.y;
        egB[2] = (a0.z + frB * (b0.z - a0.z)) * g0.z;
        egB[3] = (a0.w + frB * (b0.w - a0.w)) * g0.w;
        egB[4] = (a1.x + frB * (b1.x - a1.x)) * g1.x;
        egB[5] = (a1.y + frB * (b1.y - a1.y)) * g1.y;
        egB[6] = (a1.z + frB * (b1.z - a1.z)) * g1.z;
        egB[7] = (a1.w + frB * (b1.w - a1.w)) * g1.w;
    }

    float hA[8], hB[8];
    {
        const float4* ap = (const float4*)&g_a[iA * 32 + c0];
        const float4* bp = (const float4*)&g_b[jA * 32 + c0];
        float4 a0 = ap[0], a1 = ap[1], b0 = bp[0], b1 = bp[1];
        hA[0] = siluf(a0.x + b0.x); hA[1] = siluf(a0.y + b0.y);
        hA[2] = siluf(a0.z + b0.z); hA[3] = siluf(a0.w + b0.w);
        hA[4] = siluf(a1.x + b1.x); hA[5] = siluf(a1.y + b1.y);
        hA[6] = siluf(a1.z + b1.z); hA[7] = siluf(a1.w + b1.w);
    }
    {
        const float4* ap = (const float4*)&g_a[iB * 32 + c0];
        const float4* bp = (const float4*)&g_b[jB * 32 + c0];
        float4 a0 = ap[0], a1 = ap[1], b0 = bp[0], b1 = bp[1];
        hB[0] = siluf(a0.x + b0.x); hB[1] = siluf(a0.y + b0.y);
        hB[2] = siluf(a0.z + b0.z); hB[3] = siluf(a0.w + b0.w);
        hB[4] = siluf(a1.x + b1.x); hB[5] = siluf(a1.y + b1.y);
        hB[6] = siluf(a1.z + b1.z); hB[7] = siluf(a1.w + b1.w);
    }

    u64 mmA[4], mmB[4];
    #pragma unroll
    for (int p = 0; p < 4; p++) {
        u64 bb = pack2(sB2[c0 + 2 * p], sB2[c0 + 2 * p + 1]);
        mmA[p] = bb; mmB[p] = bb;
    }
    MV32X2(mmA, mmB, hA, hB, sW2, c0);

    float mA[8], mB[8];
    {
        float t0, t1;
        unpack2(mmA[0], t0, t1); mA[0] = siluf(t0) * egA[0]; mA[1] = siluf(t1) * egA[1];
        unpack2(mmA[1], t0, t1); mA[2] = siluf(t0) * egA[2]; mA[3] = siluf(t1) * egA[3];
        unpack2(mmA[2], t0, t1); mA[4] = siluf(t0) * egA[4]; mA[5] = siluf(t1) * egA[5];
        unpack2(mmA[3], t0, t1); mA[6] = siluf(t0) * egA[6]; mA[7] = siluf(t1) * egA[7];
        unpack2(mmB[0], t0, t1); mB[0] = siluf(t0) * egB[0]; mB[1] = siluf(t1) * egB[1];
        unpack2(mmB[1], t0, t1); mB[2] = siluf(t0) * egB[2]; mB[3] = siluf(t1) * egB[3];
        unpack2(mmB[2], t0, t1); mB[4] = siluf(t0) * egB[4]; mB[5] = siluf(t1) * egB[5];
        unpack2(mmB[3], t0, t1); mB[6] = siluf(t0) * egB[6]; mB[7] = siluf(t1) * egB[7];
    }

    // scatter m_ij early (retire atomics while MV2 runs)
    float* maccA = &g_macc[jA * 32 + c0];
    red_v4(maccA,     mA[0], mA[1], mA[2], mA[3]);
    red_v4(maccA + 4, mA[4], mA[5], mA[6], mA[7]);
    float* maccB = &g_macc[jB * 32 + c0];
    red_v4(maccB,     mB[0], mB[1], mB[2], mB[3]);
    red_v4(maccB + 4, mB[4], mB[5], mB[6], mB[7]);

    u64 stA[4], stB[4];
    #pragma unroll
    for (int p = 0; p < 4; p++) {
        u64 bb = pack2(sCB1[c0 + 2 * p], sCB1[c0 + 2 * p + 1]);
        stA[p] = bb; stB[p] = bb;
    }
    MV32X2(stA, stB, mA, mB, sC1, c0);

    float spA = 0.0f, spB = 0.0f;
    #pragma unroll
    for (int p = 0; p < 4; p++) {
        float t0, t1;
        float w0 = sC2[c0 + 2 * p], w1 = sC2[c0 + 2 * p + 1];
        unpack2(stA[p], t0, t1);
        spA += siluf(t0) * w0 + siluf(t1) * w1;
        unpack2(stB[p], t0, t1);
        spB += siluf(t0) * w0 + siluf(t1) * w1;
    }
    spA += __shfl_xor_sync(0xffffffffu, spA, 1);
    spA += __shfl_xor_sync(0xffffffffu, spA, 2);
    spB += __shfl_xor_sync(0xffffffffu, spB, 1);
    spB += __shfl_xor_sync(0xffffffffu, spB, 2);
    float sA = spA + sCB2;
    float sB = spB + sCB2;

    if (sub == 0) {
        red_v4(&g_pacc[jA * 4], dxA * sA, dyA * sA, dzA * sA, 1.0f);
        red_v4(&g_pacc[jB * 4], dxB * sB, dyB * sB, dzB * sB, 1.0f);
    }
}

// ---------------- K4: combine + outputs (FFMA2) ----------------
__global__ void __launch_bounds__(256) k_final(
        const float* __restrict__ pos,
        const float* __restrict__ comb_w1, const float* __restrict__ cb1,
        const float* __restrict__ comb_w2, const float* __restrict__ cb2,
        float* __restrict__ outx, float* __restrict__ outp) {
    __shared__ __align__(16) float sW1[64 * 32];
    __shared__ __align__(16) float sW2[32 * 32];
    int tid = threadIdx.x;
    for (int k = tid; k < 2048; k += 256) sW1[k] = comb_w1[k];
    for (int k = tid; k < 1024; k += 256) sW2[k] = comb_w2[k];
    __syncthreads();

    int sub = tid & 3;
    int c0 = sub * 8;
    int n = blockIdx.x * 64 + (tid >> 2);
    if (n >= N_NODES) return;   // warp-uniform

    const float* src = (sub < 2) ? &g_xm[n * 32] : &g_macc[n * 32];
    const float4* ip = (const float4*)&src[(sub & 1) * 16];
    float4 i0 = ip[0], i1 = ip[1], i2 = ip[2], i3 = ip[3];
    float inv[16] = {i0.x, i0.y, i0.z, i0.w, i1.x, i1.y, i1.z, i1.w,
                     i2.x, i2.y, i2.z, i2.w, i3.x, i3.y, i3.z, i3.w};

    u64 acc[4];
    #pragma unroll
    for (int p = 0; p < 4; p++) acc[p] = pack2(cb1[c0 + 2 * p], cb1[c0 + 2 * p + 1]);
    #pragma unroll
    for (int kk = 0; kk < 64; kk++) {
        float v = __shfl_sync(0xffffffffu, inv[kk & 15], kk >> 4, 4);
        u64 vv = pack2(v, v);
        const ulonglong2* wp = (const ulonglong2*)&sW1[kk * 32 + c0];
        ulonglong2 w0 = wp[0], w1 = wp[1];
        ffma2(acc[0], w0.x, vv); ffma2(acc[1], w0.y, vv);
        ffma2(acc[2], w1.x, vv); ffma2(acc[3], w1.y, vv);
    }
    float hh[8];
    {
        float t0, t1;
        unpack2(acc[0], t0, t1); hh[0] = siluf(t0); hh[1] = siluf(t1);
        unpack2(acc[1], t0, t1); hh[2] = siluf(t0); hh[3] = siluf(t1);
        unpack2(acc[2], t0, t1); hh[4] = siluf(t0); hh[5] = siluf(t1);
        unpack2(acc[3], t0, t1); hh[6] = siluf(t0); hh[7] = siluf(t1);
    }

    u64 acc2[4];
    #pragma unroll
    for (int p = 0; p < 4; p++) acc2[p] = pack2(cb2[c0 + 2 * p], cb2[c0 + 2 * p + 1]);
    #pragma unroll
    for (int kk = 0; kk < 32; kk++) {
        float v = __shfl_sync(0xffffffffu, hh[kk & 7], kk >> 3, 4);
        u64 vv = pack2(v, v);
        const ulonglong2* wp = (const ulonglong2*)&sW2[kk * 32 + c0];
        ulonglong2 w0 = wp[0], w1 = wp[1];
        ffma2(acc2[0], w0.x, vv); ffma2(acc2[1], w0.y, vv);
        ffma2(acc2[2], w1.x, vv); ffma2(acc2[3], w1.y, vv);
    }
    float cc[8];
    {
        float t0, t1;
        unpack2(acc2[0], t0, t1); cc[0] = t0; cc[1] = t1;
        unpack2(acc2[1], t0, t1); cc[2] = t0; cc[3] = t1;
        unpack2(acc2[2], t0, t1); cc[4] = t0; cc[5] = t1;
        unpack2(acc2[3], t0, t1); cc[6] = t0; cc[7] = t1;
    }

    const float4* xmp = (const float4*)&g_xm[n * 32 + c0];
    float4 xm0 = xmp[0], xm1 = xmp[1];
    float4 o0, o1;
    o0.x = siluf(xm0.x + cc[0]); o0.y = siluf(xm0.y + cc[1]);
    o0.z = siluf(xm0.z + cc[2]); o0.w = siluf(xm0.w + cc[3]);
    o1.x = siluf(xm1.x + cc[4]); o1.y = siluf(xm1.y + cc[5]);
    o1.z = siluf(xm1.z + cc[6]); o1.w = siluf(xm1.w + cc[7]);
    float4* op = (float4*)&outx[n * 32 + c0];
    op[0] = o0; op[1] = o1;

    if (sub == 0) {
        float4 pa = *(const float4*)&g_pacc[n * 4];
        float inv_c = 1.0f / fmaxf(pa.w, 1.0f);
        outp[n * 3 + 0] = pos[n * 3 + 0] + pa.x * inv_c;
        outp[n * 3 + 1] = pos[n * 3 + 1] + pa.y * inv_c;
        outp[n * 3 + 2] = pos[n * 3 + 2] + pa.z * inv_c;
    }
}

// ---------------- launch ----------------
extern "C" void kernel_launch(void* const* d_in, const int* in_sizes, int n_in,
                              void* d_out, int out_size) {
    const float* x        = (const float*)d_in[0];
    const int*   ei       = (const int*)d_in[1];
    const float* pos      = (const float*)d_in[2];
    const float* time     = (const float*)d_in[3];
    const int*   batch    = (const int*)d_in[4];
    const float* means    = (const float*)d_in[5];
    const float* betas    = (const float*)d_in[6];
    const float* w_dist   = (const float*)d_in[7];
    const float* msg_w1   = (const float*)d_in[8];
    const float* msg_b1   = (const float*)d_in[9];
    const float* msg_w2   = (const float*)d_in[10];
    const float* msg_b2   = (const float*)d_in[11];
    const float* gate_w   = (const float*)d_in[12];
    const float* gate_b   = (const float*)d_in[13];
    const float* time_w1  = (const float*)d_in[14];
    const float* time_b1  = (const float*)d_in[15];
    const float* time_w2  = (const float*)d_in[16];
    const float* time_b2  = (const float*)d_in[17];
    const float* comb_w1  = (const float*)d_in[18];
    const float* comb_b1  = (const float*)d_in[19];
    const float* comb_w2  = (const float*)d_in[20];
    const float* comb_b2  = (const float*)d_in[21];
    const float* coord_w1 = (const float*)d_in[22];
    const float* coord_b1 = (const float*)d_in[23];
    const float* coord_w2 = (const float*)d_in[24];
    const float* coord_b2 = (const float*)d_in[25];

    float* outx = (float*)d_out;
    float* outp = (float*)d_out + N_NODES * 32;

    k_time<<<G_GRAPHS / 4, 256>>>(time, time_w1, time_b1, time_w2, time_b2);
    k_node<<<NODE_BLOCKS + TAB / 8, 256>>>(x, batch, pos, msg_w1, msg_b1,
                                           gate_w, gate_b, means, betas, w_dist);
    k_edge<<<E_EDGES / 64, 128>>>(ei, msg_w2, msg_b2,
                                  coord_w1, coord_b1, coord_w2, coord_b2);
    k_final<<<NODE_BLOCKS, 256>>>(pos, comb_w1, comb_b1, comb_w2, comb_b2,
                                  outx, outp);
}

// round 7
// speedup vs baseline: 1.6148x; 1.0412x over previous
#include <cuda_runtime.h>
#include <math.h>

#define N_NODES 100000
#define E_EDGES 800000
#define G_GRAPHS 512
#define HID 32
#define D_CUT 5.0f
#define TAB 8192
#define NODE_BLOCKS 1563   // ceil(100000/64)

typedef unsigned long long u64;

// ---------------- scratch (static, no allocation) ----------------
__device__ __align__(16) float g_ss[G_GRAPHS * 64];
__device__ __align__(16) float g_xm[N_NODES * 32];
__device__ __align__(16) float g_a[N_NODES * 32];
__device__ __align__(16) float g_b[N_NODES * 32];
__device__ __align__(16) float g_gate[N_NODES * 32];
__device__ __align__(16) float g_macc[N_NODES * 32];
__device__ __align__(16) float g_pacc[N_NODES * 4];
__device__ __align__(16) float4 g_pos4[N_NODES];
__device__ __align__(16) float g_tab[TAB * 32];

__device__ __forceinline__ float siluf(float v) { return v / (1.0f + __expf(-v)); }
__device__ __forceinline__ float sigmf(float v) { return 1.0f / (1.0f + __expf(-v)); }

__device__ __forceinline__ void red_v4(float* p, float a, float b, float c, float d) {
    asm volatile("red.global.add.v4.f32 [%0], {%1,%2,%3,%4};"
                 :: "l"(p), "f"(a), "f"(b), "f"(c), "f"(d) : "memory");
}

__device__ __forceinline__ u64 pack2(float lo, float hi) {
    u64 r; asm("mov.b64 %0, {%1, %2};" : "=l"(r) : "f"(lo), "f"(hi)); return r;
}
__device__ __forceinline__ void unpack2(u64 v, float& lo, float& hi) {
    asm("mov.b64 {%0, %1}, %2;" : "=f"(lo), "=f"(hi) : "l"(v));
}
__device__ __forceinline__ void ffma2(u64& d, u64 a, u64 b) {
    asm("fma.rn.f32x2 %0, %1, %2, %0;" : "+l"(d) : "l"(a), "l"(b));
}

// ---------------- K1: time MLP + dist_emb table (fused) ----------------
__global__ void __launch_bounds__(256) k_time(
        const float* __restrict__ time,
        const float* __restrict__ w1, const float* __restrict__ b1,
        const float* __restrict__ w2, const float* __restrict__ b2,
        const float* __restrict__ means, const float* __restrict__ betas,
        const float* __restrict__ w_dist) {
    int tid = threadIdx.x;
    if (blockIdx.x >= G_GRAPHS / 4) {
        // ---- dist_emb table branch ----
        __shared__ float sW[1024];
        __shared__ float sMu[32], sBeta[32];
        for (int k = tid; k < 1024; k += 256) sW[k] = w_dist[k];
        if (tid < 32) { sMu[tid] = means[tid]; sBeta[tid] = betas[tid]; }
        __syncthreads();
        int r = (blockIdx.x - G_GRAPHS / 4) * 8 + (tid >> 5);
        int c = tid & 31;
        float d = (float)r * (D_CUT / (float)(TAB - 1));
        float cutoff = 0.5f * (__cosf(d * (3.14159265358979f / D_CUT)) + 1.0f);
        float ed = __expf(-d);
        float acc = 0.0f;
        #pragma unroll 8
        for (int k = 0; k < 32; k++) {
            float t = ed - sMu[k];
            acc += __expf(-sBeta[k] * t * t) * sW[k * 32 + c];
        }
        g_tab[r * 32 + c] = cutoff * acc;
        return;
    }
    __shared__ float trow[4][128];
    __shared__ float hid[4][64];
    int gsub = tid >> 6;
    int t = tid & 63;
    int g = blockIdx.x * 4 + gsub;
    trow[gsub][t]      = time[g * 128 + t];
    trow[gsub][t + 64] = time[g * 128 + 64 + t];
    __syncthreads();
    float acc = b1[t];
    #pragma unroll 8
    for (int k = 0; k < 128; k++) acc += trow[gsub][k] * w1[k * 64 + t];
    hid[gsub][t] = siluf(acc);
    __syncthreads();
    float acc2 = b2[t];
    #pragma unroll 8
    for (int k = 0; k < 64; k++) acc2 += hid[gsub][k] * w2[k * 64 + t];
    g_ss[g * 64 + t] = acc2;
}

// ---------------- K2: per-node precompute, NE=2 nodes per 4-lane group ------
// 128 threads = 32 groups x 4 lanes; group handles nodes n0, n0+1.
// Per kk: 2 shfl + 6 LDS.128 (shared over both nodes) + 24 ffma2.
__global__ void __launch_bounds__(128) k_node(
        const float* __restrict__ x, const int* __restrict__ batch,
        const float* __restrict__ pos,
        const float* __restrict__ msg_w1, const float* __restrict__ msg_b1,
        const float* __restrict__ gate_w, const float* __restrict__ gate_b) {
    __shared__ __align__(16) float sW1[64 * 32];
    __shared__ __align__(16) float sWg[32 * 32];
    int tid = threadIdx.x;
    for (int k = tid; k < 2048; k += 128) sW1[k] = msg_w1[k];
    for (int k = tid; k < 1024; k += 128) sWg[k] = gate_w[k];
    __syncthreads();

    int sub = tid & 3;
    int c0 = sub * 8;
    int n0 = blockIdx.x * 64 + (tid >> 2) * 2;
    if (n0 >= N_NODES) return;   // warp-uniform: 16 nodes/warp, 16 | 100000
    int n1 = n0 + 1;

    float xmA[8], xmB[8];
    {
        int bn = batch[n0];
        const float4* scp = (const float4*)&g_ss[bn * 64 + c0];
        const float4* shp = (const float4*)&g_ss[bn * 64 + 32 + c0];
        const float4* xp  = (const float4*)&x[n0 * 32 + c0];
        float4 sc0 = scp[0], sc1 = scp[1];
        float4 sh0 = shp[0], sh1 = shp[1];
        float4 x0 = xp[0], x1 = xp[1];
        xmA[0] = siluf(x0.x * (1.0f + sc0.x) + sh0.x);
        xmA[1] = siluf(x0.y * (1.0f + sc0.y) + sh0.y);
        xmA[2] = siluf(x0.z * (1.0f + sc0.z) + sh0.z);
        xmA[3] = siluf(x0.w * (1.0f + sc0.w) + sh0.w);
        xmA[4] = siluf(x1.x * (1.0f + sc1.x) + sh1.x);
        xmA[5] = siluf(x1.y * (1.0f + sc1.y) + sh1.y);
        xmA[6] = siluf(x1.z * (1.0f + sc1.z) + sh1.z);
        xmA[7] = siluf(x1.w * (1.0f + sc1.w) + sh1.w);
    }
    {
        int bn = batch[n1];
        const float4* scp = (const float4*)&g_ss[bn * 64 + c0];
        const float4* shp = (const float4*)&g_ss[bn * 64 + 32 + c0];
        const float4* xp  = (const float4*)&x[n1 * 32 + c0];
        float4 sc0 = scp[0], sc1 = scp[1];
        float4 sh0 = shp[0], sh1 = shp[1];
        float4 x0 = xp[0], x1 = xp[1];
        xmB[0] = siluf(x0.x * (1.0f + sc0.x) + sh0.x);
        xmB[1] = siluf(x0.y * (1.0f + sc0.y) + sh0.y);
        xmB[2] = siluf(x0.z * (1.0f + sc0.z) + sh0.z);
        xmB[3] = siluf(x0.w * (1.0f + sc0.w) + sh0.w);
        xmB[4] = siluf(x1.x * (1.0f + sc1.x) + sh1.x);
        xmB[5] = siluf(x1.y * (1.0f + sc1.y) + sh1.y);
        xmB[6] = siluf(x1.z * (1.0f + sc1.z) + sh1.z);
        xmB[7] = siluf(x1.w * (1.0f + sc1.w) + sh1.w);
    }

    u64 aA[4], bA[4], gA[4], aB[4], bB[4], gB[4];
    #pragma unroll
    for (int p = 0; p < 4; p++) {
        u64 mb = pack2(msg_b1[c0 + 2 * p], msg_b1[c0 + 2 * p + 1]);
        u64 gb = pack2(gate_b[c0 + 2 * p], gate_b[c0 + 2 * p + 1]);
        aA[p] = mb; aB[p] = mb;
        bA[p] = 0ULL; bB[p] = 0ULL;
        gA[p] = gb; gB[p] = gb;
    }
    #pragma unroll
    for (int kk = 0; kk < 32; kk++) {
        float vA = __shfl_sync(0xffffffffu, xmA[kk & 7], kk >> 3, 4);
        float vB = __shfl_sync(0xffffffffu, xmB[kk & 7], kk >> 3, 4);
        u64 vvA = pack2(vA, vA);
        u64 vvB = pack2(vB, vB);
        const ulonglong2* wa = (const ulonglong2*)&sW1[kk * 32 + c0];
        const ulonglong2* wb = (const ulonglong2*)&sW1[(32 + kk) * 32 + c0];
        const ulonglong2* wg = (const ulonglong2*)&sWg[kk * 32 + c0];
        ulonglong2 wa0 = wa[0], wa1 = wa[1];
        ulonglong2 wb0 = wb[0], wb1 = wb[1];
        ulonglong2 wg0 = wg[0], wg1 = wg[1];
        ffma2(aA[0], wa0.x, vvA); ffma2(aA[1], wa0.y, vvA);
        ffma2(aA[2], wa1.x, vvA); ffma2(aA[3], wa1.y, vvA);
        ffma2(aB[0], wa0.x, vvB); ffma2(aB[1], wa0.y, vvB);
        ffma2(aB[2], wa1.x, vvB); ffma2(aB[3], wa1.y, vvB);
        ffma2(bA[0], wb0.x, vvA); ffma2(bA[1], wb0.y, vvA);
        ffma2(bA[2], wb1.x, vvA); ffma2(bA[3], wb1.y, vvA);
        ffma2(bB[0], wb0.x, vvB); ffma2(bB[1], wb0.y, vvB);
        ffma2(bB[2], wb1.x, vvB); ffma2(bB[3], wb1.y, vvB);
        ffma2(gA[0], wg0.x, vvA); ffma2(gA[1], wg0.y, vvA);
        ffma2(gA[2], wg1.x, vvA); ffma2(gA[3], wg1.y, vvA);
        ffma2(gB[0], wg0.x, vvB); ffma2(gB[1], wg0.y, vvB);
        ffma2(gB[2], wg1.x, vvB); ffma2(gB[3], wg1.y, vvB);
    }

    // stores (node A)
    {
        float4* oxm = (float4*)&g_xm[n0 * 32 + c0];
        oxm[0] = make_float4(xmA[0], xmA[1], xmA[2], xmA[3]);
        oxm[1] = make_float4(xmA[4], xmA[5], xmA[6], xmA[7]);
        ulonglong2* oa = (ulonglong2*)&g_a[n0 * 32 + c0];
        oa[0] = make_ulonglong2(aA[0], aA[1]); oa[1] = make_ulonglong2(aA[2], aA[3]);
        ulonglong2* ob = (ulonglong2*)&g_b[n0 * 32 + c0];
        ob[0] = make_ulonglong2(bA[0], bA[1]); ob[1] = make_ulonglong2(bA[2], bA[3]);
        float gg[8];
        unpack2(gA[0], gg[0], gg[1]); unpack2(gA[1], gg[2], gg[3]);
        unpack2(gA[2], gg[4], gg[5]); unpack2(gA[3], gg[6], gg[7]);
        float4* og = (float4*)&g_gate[n0 * 32 + c0];
        og[0] = make_float4(sigmf(gg[0]), sigmf(gg[1]), sigmf(gg[2]), sigmf(gg[3]));
        og[1] = make_float4(sigmf(gg[4]), sigmf(gg[5]), sigmf(gg[6]), sigmf(gg[7]));
    }
    // stores (node B)
    {
        float4* oxm = (float4*)&g_xm[n1 * 32 + c0];
        oxm[0] = make_float4(xmB[0], xmB[1], xmB[2], xmB[3]);
        oxm[1] = make_float4(xmB[4], xmB[5], xmB[6], xmB[7]);
        ulonglong2* oa = (ulonglong2*)&g_a[n1 * 32 + c0];
        oa[0] = make_ulonglong2(aB[0], aB[1]); oa[1] = make_ulonglong2(aB[2], aB[3]);
        ulonglong2* ob = (ulonglong2*)&g_b[n1 * 32 + c0];
        ob[0] = make_ulonglong2(bB[0], bB[1]); ob[1] = make_ulonglong2(bB[2], bB[3]);
        float gg[8];
        unpack2(gB[0], gg[0], gg[1]); unpack2(gB[1], gg[2], gg[3]);
        unpack2(gB[2], gg[4], gg[5]); unpack2(gB[3], gg[6], gg[7]);
        float4* og = (float4*)&g_gate[n1 * 32 + c0];
        og[0] = make_float4(sigmf(gg[0]), sigmf(gg[1]), sigmf(gg[2]), sigmf(gg[3]));
        og[1] = make_float4(sigmf(gg[4]), sigmf(gg[5]), sigmf(gg[6]), sigmf(gg[7]));
    }

    float4 z = make_float4(0.f, 0.f, 0.f, 0.f);
    float4* mzA = (float4*)&g_macc[n0 * 32 + c0];
    mzA[0] = z; mzA[1] = z;
    float4* mzB = (float4*)&g_macc[n1 * 32 + c0];
    mzB[0] = z; mzB[1] = z;
    if (sub == 0) {
        *(float4*)&g_pacc[n0 * 4] = z;
        *(float4*)&g_pacc[n1 * 4] = z;
        g_pos4[n0] = make_float4(pos[n0 * 3], pos[n0 * 3 + 1], pos[n0 * 3 + 2], 0.0f);
        g_pos4[n1] = make_float4(pos[n1 * 3], pos[n1 * 3 + 1], pos[n1 * 3 + 2], 0.0f);
    }
}

// ---------------- K3: edge kernel (NE=2, 128 threads, FFMA2) ----------------
#define MV32X2(accA, accB, inA, inB, W, c0)                                      \
    do {                                                                         \
        _Pragma("unroll")                                                        \
        for (int kk = 0; kk < 32; kk++) {                                        \
            float vA = __shfl_sync(0xffffffffu, inA[kk & 7], kk >> 3, 4);        \
            float vB = __shfl_sync(0xffffffffu, inB[kk & 7], kk >> 3, 4);        \
            u64 vvA = pack2(vA, vA);                                             \
            u64 vvB = pack2(vB, vB);                                             \
            const ulonglong2* wp = (const ulonglong2*)&W[kk * 32 + c0];          \
            ulonglong2 w0 = wp[0], w1 = wp[1];                                   \
            ffma2(accA[0], w0.x, vvA); ffma2(accA[1], w0.y, vvA);                \
            ffma2(accA[2], w1.x, vvA); ffma2(accA[3], w1.y, vvA);                \
            ffma2(accB[0], w0.x, vvB); ffma2(accB[1], w0.y, vvB);                \
            ffma2(accB[2], w1.x, vvB); ffma2(accB[3], w1.y, vvB);                \
        }                                                                        \
    } while (0)

__global__ void __launch_bounds__(128) k_edge(
        const int* __restrict__ ei,
        const float* __restrict__ msg_w2, const float* __restrict__ msg_b2,
        const float* __restrict__ coord_w1, const float* __restrict__ coord_b1,
        const float* __restrict__ coord_w2, const float* __restrict__ coord_b2) {
    __shared__ __align__(16) float sW2[1024];
    __shared__ __align__(16) float sC1[1024];
    __shared__ float sC2[32], sB2[32], sCB1[32];
    __shared__ float sCB2;

    int tid = threadIdx.x;
    for (int k = tid; k < 1024; k += 128) {
        sW2[k] = msg_w2[k];
        sC1[k] = coord_w1[k];
    }
    if (tid < 32) {
        sC2[tid]  = coord_w2[tid];
        sB2[tid]  = msg_b2[tid];
        sCB1[tid] = coord_b1[tid];
    }
    if (tid == 0) sCB2 = coord_b2[0];
    __syncthreads();

    int sub = tid & 3;
    int c0 = sub * 8;
    int e0 = blockIdx.x * 64 + (tid >> 2) * 2;

    int2 ip = *(const int2*)&ei[e0];
    int2 jp = *(const int2*)&ei[E_EDGES + e0];
    int iA = ip.x, iB = ip.y;
    int jA = jp.x, jB = jp.y;

    float4 piA = g_pos4[iA], pjA = g_pos4[jA];
    float4 piB = g_pos4[iB], pjB = g_pos4[jB];
    float dxA = piA.x - pjA.x, dyA = piA.y - pjA.y, dzA = piA.z - pjA.z;
    float dxB = piB.x - pjB.x, dyB = piB.y - pjB.y, dzB = piB.z - pjB.z;
    float distA = sqrtf(dxA * dxA + dyA * dyA + dzA * dzA);
    float distB = sqrtf(dxB * dxB + dyB * dyB + dzB * dzB);

    float uA = fminf(distA, D_CUT) * ((float)(TAB - 1) / D_CUT);
    float uB = fminf(distB, D_CUT) * ((float)(TAB - 1) / D_CUT);
    int i0A = min((int)uA, TAB - 2);
    int i0B = min((int)uB, TAB - 2);
    float frA = uA - (float)i0A;
    float frB = uB - (float)i0B;

    const float4* tA0 = (const float4*)&g_tab[i0A * 32 + c0];
    const float4* tA1 = (const float4*)&g_tab[(i0A + 1) * 32 + c0];
    const float4* tB0 = (const float4*)&g_tab[i0B * 32 + c0];
    const float4* tB1 = (const float4*)&g_tab[(i0B + 1) * 32 + c0];
    const float4* gAp = (const float4*)&g_gate[jA * 32 + c0];
    const float4* gBp = (const float4*)&g_gate[jB * 32 + c0];

    float egA[8], egB[8];
    {
        float4 a0 = tA0[0], a1 = tA0[1], b0 = tA1[0], b1 = tA1[1];
        float4 g0 = gAp[0], g1 = gAp[1];
        egA[0] = (a0.x + frA * (b0.x - a0.x)) * g0.x;
        egA[1] = (a0.y + frA * (b0.y - a0.y)) * g0.y;
        egA[2] = (a0.z + frA * (b0.z - a0.z)) * g0.z;
        egA[3] = (a0.w + frA * (b0.w - a0.w)) * g0.w;
        egA[4] = (a1.x + frA * (b1.x - a1.x)) * g1.x;
        egA[5] = (a1.y + frA * (b1.y - a1.y)) * g1.y;
        egA[6] = (a1.z + frA * (b1.z - a1.z)) * g1.z;
        egA[7] = (a1.w + frA * (b1.w - a1.w)) * g1.w;
    }
    {
        float4 a0 = tB0[0], a1 = tB0[1], b0 = tB1[0], b1 = tB1[1];
        float4 g0 = gBp[0], g1 = gBp[1];
        egB[0] = (a0.x + frB * (b0.x - a0.x)) * g0.x;
        egB[1] = (a0.y + frB * (b0.y - a0.y)) * g0.y;
        egB[2] = (a0.z + frB * (b0.z - a0.z)) * g0.z;
        egB[3] = (a0.w + frB * (b0.w - a0.w)) * g0.w;
        egB[4] = (a1.x + frB * (b1.x - a1.x)) * g1.x;
        egB[5] = (a1.y + frB * (b1.y - a1.y)) * g1.y;
        egB[6] = (a1.z + frB * (b1.z - a1.z)) * g1.z;
        egB[7] = (a1.w + frB * (b1.w - a1.w)) * g1.w;
    }

    float hA[8], hB[8];
    {
        const float4* ap = (const float4*)&g_a[iA * 32 + c0];
        const float4* bp = (const float4*)&g_b[jA * 32 + c0];
        float4 a0 = ap[0], a1 = ap[1], b0 = bp[0], b1 = bp[1];
        hA[0] = siluf(a0.x + b0.x); hA[1] = siluf(a0.y + b0.y);
        hA[2] = siluf(a0.z + b0.z); hA[3] = siluf(a0.w + b0.w);
        hA[4] = siluf(a1.x + b1.x); hA[5] = siluf(a1.y + b1.y);
        hA[6] = siluf(a1.z + b1.z); hA[7] = siluf(a1.w + b1.w);
    }
    {
        const float4* ap = (const float4*)&g_a[iB * 32 + c0];
        const float4* bp = (const float4*)&g_b[jB * 32 + c0];
        float4 a0 = ap[0], a1 = ap[1], b0 = bp[0], b1 = bp[1];
        hB[0] = siluf(a0.x + b0.x); hB[1] = siluf(a0.y + b0.y);
        hB[2] = siluf(a0.z + b0.z); hB[3] = siluf(a0.w + b0.w);
        hB[4] = siluf(a1.x + b1.x); hB[5] = siluf(a1.y + b1.y);
        hB[6] = siluf(a1.z + b1.z); hB[7] = siluf(a1.w + b1.w);
    }

    u64 mmA[4], mmB[4];
    #pragma unroll
    for (int p = 0; p < 4; p++) {
        u64 bb = pack2(sB2[c0 + 2 * p], sB2[c0 + 2 * p + 1]);
        mmA[p] = bb; mmB[p] = bb;
    }
    MV32X2(mmA, mmB, hA, hB, sW2, c0);

    float mA[8], mB[8];
    {
        float t0, t1;
        unpack2(mmA[0], t0, t1); mA[0] = siluf(t0) * egA[0]; mA[1] = siluf(t1) * egA[1];
        unpack2(mmA[1], t0, t1); mA[2] = siluf(t0) * egA[2]; mA[3] = siluf(t1) * egA[3];
        unpack2(mmA[2], t0, t1); mA[4] = siluf(t0) * egA[4]; mA[5] = siluf(t1) * egA[5];
        unpack2(mmA[3], t0, t1); mA[6] = siluf(t0) * egA[6]; mA[7] = siluf(t1) * egA[7];
        unpack2(mmB[0], t0, t1); mB[0] = siluf(t0) * egB[0]; mB[1] = siluf(t1) * egB[1];
        unpack2(mmB[1], t0, t1); mB[2] = siluf(t0) * egB[2]; mB[3] = siluf(t1) * egB[3];
        unpack2(mmB[2], t0, t1); mB[4] = siluf(t0) * egB[4]; mB[5] = siluf(t1) * egB[5];
        unpack2(mmB[3], t0, t1); mB[6] = siluf(t0) * egB[6]; mB[7] = siluf(t1) * egB[7];
    }

    float* maccA = &g_macc[jA * 32 + c0];
    red_v4(maccA,     mA[0], mA[1], mA[2], mA[3]);
    red_v4(maccA + 4, mA[4], mA[5], mA[6], mA[7]);
    float* maccB = &g_macc[jB * 32 + c0];
    red_v4(maccB,     mB[0], mB[1], mB[2], mB[3]);
    red_v4(maccB + 4, mB[4], mB[5], mB[6], mB[7]);

    u64 stA[4], stB[4];
    #pragma unroll
    for (int p = 0; p < 4; p++) {
        u64 bb = pack2(sCB1[c0 + 2 * p], sCB1[c0 + 2 * p + 1]);
        stA[p] = bb; stB[p] = bb;
    }
    MV32X2(stA, stB, mA, mB, sC1, c0);

    float spA = 0.0f, spB = 0.0f;
    #pragma unroll
    for (int p = 0; p < 4; p++) {
        float t0, t1;
        float w0 = sC2[c0 + 2 * p], w1 = sC2[c0 + 2 * p + 1];
        unpack2(stA[p], t0, t1);
        spA += siluf(t0) * w0 + siluf(t1) * w1;
        unpack2(stB[p], t0, t1);
        spB += siluf(t0) * w0 + siluf(t1) * w1;
    }
    spA += __shfl_xor_sync(0xffffffffu, spA, 1);
    spA += __shfl_xor_sync(0xffffffffu, spA, 2);
    spB += __shfl_xor_sync(0xffffffffu, spB, 1);
    spB += __shfl_xor_sync(0xffffffffu, spB, 2);
    float sA = spA + sCB2;
    float sB = spB + sCB2;

    if (sub == 0) {
        red_v4(&g_pacc[jA * 4], dxA * sA, dyA * sA, dzA * sA, 1.0f);
        red_v4(&g_pacc[jB * 4], dxB * sB, dyB * sB, dzB * sB, 1.0f);
    }
}

// ---------------- K4: combine + outputs, NE=2 nodes per 4-lane group --------
__global__ void __launch_bounds__(128) k_final(
        const float* __restrict__ pos,
        const float* __restrict__ comb_w1, const float* __restrict__ cb1,
        const float* __restrict__ comb_w2, const float* __restrict__ cb2,
        float* __restrict__ outx, float* __restrict__ outp) {
    __shared__ __align__(16) float sW1[64 * 32];
    __shared__ __align__(16) float sW2[32 * 32];
    int tid = threadIdx.x;
    for (int k = tid; k < 2048; k += 128) sW1[k] = comb_w1[k];
    for (int k = tid; k < 1024; k += 128) sW2[k] = comb_w2[k];
    __syncthreads();

    int sub = tid & 3;
    int c0 = sub * 8;
    int n0 = blockIdx.x * 64 + (tid >> 2) * 2;
    if (n0 >= N_NODES) return;   // warp-uniform: 16 nodes/warp
    int n1 = n0 + 1;

    float invA[16], invB[16];
    {
        const float* src = (sub < 2) ? &g_xm[n0 * 32] : &g_macc[n0 * 32];
        const float4* ip = (const float4*)&src[(sub & 1) * 16];
        float4 i0 = ip[0], i1 = ip[1], i2 = ip[2], i3 = ip[3];
        invA[0] = i0.x; invA[1] = i0.y; invA[2] = i0.z; invA[3] = i0.w;
        invA[4] = i1.x; invA[5] = i1.y; invA[6] = i1.z; invA[7] = i1.w;
        invA[8] = i2.x; invA[9] = i2.y; invA[10] = i2.z; invA[11] = i2.w;
        invA[12] = i3.x; invA[13] = i3.y; invA[14] = i3.z; invA[15] = i3.w;
    }
    {
        const float* src = (sub < 2) ? &g_xm[n1 * 32] : &g_macc[n1 * 32];
        const float4* ip = (const float4*)&src[(sub & 1) * 16];
        float4 i0 = ip[0], i1 = ip[1], i2 = ip[2], i3 = ip[3];
        invB[0] = i0.x; invB[1] = i0.y; invB[2] = i0.z; invB[3] = i0.w;
        invB[4] = i1.x; invB[5] = i1.y; invB[6] = i1.z; invB[7] = i1.w;
        invB[8] = i2.x; invB[9] = i2.y; invB[10] = i2.z; invB[11] = i2.w;
        invB[12] = i3.x; invB[13] = i3.y; invB[14] = i3.z; invB[15] = i3.w;
    }

    u64 accA[4], accB[4];
    #pragma unroll
    for (int p = 0; p < 4; p++) {
        u64 bb = pack2(cb1[c0 + 2 * p], cb1[c0 + 2 * p + 1]);
        accA[p] = bb; accB[p] = bb;
    }
    #pragma unroll
    for (int kk = 0; kk < 64; kk++) {
        float vA = __shfl_sync(0xffffffffu, invA[kk & 15], kk >> 4, 4);
        float vB = __shfl_sync(0xffffffffu, invB[kk & 15], kk >> 4, 4);
        u64 vvA = pack2(vA, vA);
        u64 vvB = pack2(vB, vB);
        const ulonglong2* wp = (const ulonglong2*)&sW1[kk * 32 + c0];
        ulonglong2 w0 = wp[0], w1 = wp[1];
        ffma2(accA[0], w0.x, vvA); ffma2(accA[1], w0.y, vvA);
        ffma2(accA[2], w1.x, vvA); ffma2(accA[3], w1.y, vvA);
        ffma2(accB[0], w0.x, vvB); ffma2(accB[1], w0.y, vvB);
        ffma2(accB[2], w1.x, vvB); ffma2(accB[3], w1.y, vvB);
    }
    float hhA[8], hhB[8];
    {
        float t0, t1;
        unpack2(accA[0], t0, t1); hhA[0] = siluf(t0); hhA[1] = siluf(t1);
        unpack2(accA[1], t0, t1); hhA[2] = siluf(t0); hhA[3] = siluf(t1);
        unpack2(accA[2], t0, t1); hhA[4] = siluf(t0); hhA[5] = siluf(t1);
        unpack2(accA[3], t0, t1); hhA[6] = siluf(t0); hhA[7] = siluf(t1);
        unpack2(accB[0], t0, t1); hhB[0] = siluf(t0); hhB[1] = siluf(t1);
        unpack2(accB[1], t0, t1); hhB[2] = siluf(t0); hhB[3] = siluf(t1);
        unpack2(accB[2], t0, t1); hhB[4] = siluf(t0); hhB[5] = siluf(t1);
        unpack2(accB[3], t0, t1); hhB[6] = siluf(t0); hhB[7] = siluf(t1);
    }

    u64 a2A[4], a2B[4];
    #pragma unroll
    for (int p = 0; p < 4; p++) {
        u64 bb = pack2(cb2[c0 + 2 * p], cb2[c0 + 2 * p + 1]);
        a2A[p] = bb; a2B[p] = bb;
    }
    #pragma unroll
    for (int kk = 0; kk < 32; kk++) {
        float vA = __shfl_sync(0xffffffffu, hhA[kk & 7], kk >> 3, 4);
        float vB = __shfl_sync(0xffffffffu, hhB[kk & 7], kk >> 3, 4);
        u64 vvA = pack2(vA, vA);
        u64 vvB = pack2(vB, vB);
        const ulonglong2* wp = (const ulonglong2*)&sW2[kk * 32 + c0];
        ulonglong2 w0 = wp[0], w1 = wp[1];
        ffma2(a2A[0], w0.x, vvA); ffma2(a2A[1], w0.y, vvA);
        ffma2(a2A[2], w1.x, vvA); ffma2(a2A[3], w1.y, vvA);
        ffma2(a2B[0], w0.x, vvB); ffma2(a2B[1], w0.y, vvB);
        ffma2(a2B[2], w1.x, vvB); ffma2(a2B[3], w1.y, vvB);
    }

    {
        float cc[8];
        float t0, t1;
        unpack2(a2A[0], t0, t1); cc[0] = t0; cc[1] = t1;
        unpack2(a2A[1], t0, t1); cc[2] = t0; cc[3] = t1;
        unpack2(a2A[2], t0, t1); cc[4] = t0; cc[5] = t1;
        unpack2(a2A[3], t0, t1); cc[6] = t0; cc[7] = t1;
        const float4* xmp = (const float4*)&g_xm[n0 * 32 + c0];
        float4 xm0 = xmp[0], xm1 = xmp[1];
        float4 o0, o1;
        o0.x = siluf(xm0.x + cc[0]); o0.y = siluf(xm0.y + cc[1]);
        o0.z = siluf(xm0.z + cc[2]); o0.w = siluf(xm0.w + cc[3]);
        o1.x = siluf(xm1.x + cc[4]); o1.y = siluf(xm1.y + cc[5]);
        o1.z = siluf(xm1.z + cc[6]); o1.w = siluf(xm1.w + cc[7]);
        float4* op = (float4*)&outx[n0 * 32 + c0];
        op[0] = o0; op[1] = o1;
    }
    {
        float cc[8];
        float t0, t1;
        unpack2(a2B[0], t0, t1); cc[0] = t0; cc[1] = t1;
        unpack2(a2B[1], t0, t1); cc[2] = t0; cc[3] = t1;
        unpack2(a2B[2], t0, t1); cc[4] = t0; cc[5] = t1;
        unpack2(a2B[3], t0, t1); cc[6] = t0; cc[7] = t1;
        const float4* xmp = (const float4*)&g_xm[n1 * 32 + c0];
        float4 xm0 = xmp[0], xm1 = xmp[1];
        float4 o0, o1;
        o0.x = siluf(xm0.x + cc[0]); o0.y = siluf(xm0.y + cc[1]);
        o0.z = siluf(xm0.z + cc[2]); o0.w = siluf(xm0.w + cc[3]);
        o1.x = siluf(xm1.x + cc[4]); o1.y = siluf(xm1.y + cc[5]);
        o1.z = siluf(xm1.z + cc[6]); o1.w = siluf(xm1.w + cc[7]);
        float4* op = (float4*)&outx[n1 * 32 + c0];
        op[0] = o0; op[1] = o1;
    }

    if (sub == 0) {
        float4 pa = *(const float4*)&g_pacc[n0 * 4];
        float ic = 1.0f / fmaxf(pa.w, 1.0f);
        outp[n0 * 3 + 0] = pos[n0 * 3 + 0] + pa.x * ic;
        outp[n0 * 3 + 1] = pos[n0 * 3 + 1] + pa.y * ic;
        outp[n0 * 3 + 2] = pos[n0 * 3 + 2] + pa.z * ic;
        float4 pb = *(const float4*)&g_pacc[n1 * 4];
        float ic2 = 1.0f / fmaxf(pb.w, 1.0f);
        outp[n1 * 3 + 0] = pos[n1 * 3 + 0] + pb.x * ic2;
        outp[n1 * 3 + 1] = pos[n1 * 3 + 1] + pb.y * ic2;
        outp[n1 * 3 + 2] = pos[n1 * 3 + 2] + pb.z * ic2;
    }
}

// ---------------- launch ----------------
extern "C" void kernel_launch(void* const* d_in, const int* in_sizes, int n_in,
                              void* d_out, int out_size) {
    const float* x        = (const float*)d_in[0];
    const int*   ei       = (const int*)d_in[1];
    const float* pos      = (const float*)d_in[2];
    const float* time     = (const float*)d_in[3];
    const int*   batch    = (const int*)d_in[4];
    const float* means    = (const float*)d_in[5];
    const float* betas    = (const float*)d_in[6];
    const float* w_dist   = (const float*)d_in[7];
    const float* msg_w1   = (const float*)d_in[8];
    const float* msg_b1   = (const float*)d_in[9];
    const float* msg_w2   = (const float*)d_in[10];
    const float* msg_b2   = (const float*)d_in[11];
    const float* gate_w   = (const float*)d_in[12];
    const float* gate_b   = (const float*)d_in[13];
    const float* time_w1  = (const float*)d_in[14];
    const float* time_b1  = (const float*)d_in[15];
    const float* time_w2  = (const float*)d_in[16];
    const float* time_b2  = (const float*)d_in[17];
    const float* comb_w1  = (const float*)d_in[18];
    const float* comb_b1  = (const float*)d_in[19];
    const float* comb_w2  = (const float*)d_in[20];
    const float* comb_b2  = (const float*)d_in[21];
    const float* coord_w1 = (const float*)d_in[22];
    const float* coord_b1 = (const float*)d_in[23];
    const float* coord_w2 = (const float*)d_in[24];
    const float* coord_b2 = (const float*)d_in[25];

    float* outx = (float*)d_out;
    float* outp = (float*)d_out + N_NODES * 32;

    k_time<<<G_GRAPHS / 4 + TAB / 8, 256>>>(time, time_w1, time_b1, time_w2, time_b2,
                                            means, betas, w_dist);
    k_node<<<NODE_BLOCKS, 128>>>(x, batch, pos, msg_w1, msg_b1, gate_w, gate_b);
    k_edge<<<E_EDGES / 64, 128>>>(ei, msg_w2, msg_b2,
                                  coord_w1, coord_b1, coord_w2, coord_b2);
    k_final<<<NODE_BLOCKS, 128>>>(pos, comb_w1, comb_b1, comb_w2, comb_b2,
                                  outx, outp);
}